// round 2
// baseline (speedup 1.0000x reference)
#include <cuda_runtime.h>
#include <math.h>

#define CB 4
#define CN 1024
#define CDIM 1024
#define CH 16
#define CDH 64
#define CINNER 1024
#define CVOCAB 129
#define CBH 64
#define CTOPK 256
#define CSCALE 0.125f
#define CROWS (CBH * CN) /* 65536 */

// ---------------- scratch (device globals; no allocation allowed) ----------
__device__ __align__(128) float g_q[CBH * CN * CDH];
__device__ __align__(128) float g_k[CBH * CN * CDH];
__device__ __align__(128) float g_v[CBH * CN * CDH];
__device__ __align__(128) float g_qr[(size_t)CROWS * CVOCAB];
__device__ __align__(128) float g_sc[(size_t)CBH * CN * CN]; // scores -> attn (256MB)
__device__ __align__(128) float g_t0[CBH * CN * CDH];
__device__ __align__(128) float g_t1[CBH * CN * CDH];
__device__ __align__(128) float g_res[CBH * CN * CDH];
__device__ __align__(128) float g_resT[CB * CN * CINNER];

// ---------------- generic 128x128x8 NT SGEMM: C = A(MxK) * B(NxK)^T --------
template <class Epi>
__global__ void __launch_bounds__(256)
sgemm_nt(const float* __restrict__ A, const float* __restrict__ Bm,
         long sA, long sB, int M, int Nn, int K, Epi epi)
{
    __shared__ float As[8][128];
    __shared__ float Bs[8][128];
    const int z = blockIdx.z;
    A += (long)z * sA;
    Bm += (long)z * sB;
    const int bm = blockIdx.y * 128;
    const int bn = blockIdx.x * 128;
    const int tid = threadIdx.x;
    const int ty = tid >> 4;
    const int tx = tid & 15;
    const int lr = tid >> 1;
    const int lc = (tid & 1) * 4;
    float acc[8][8];
#pragma unroll
    for (int i = 0; i < 8; i++)
#pragma unroll
        for (int j = 0; j < 8; j++) acc[i][j] = 0.f;

    const float* Ap = A + (long)(bm + lr) * K + lc;
    const float* Bp = Bm + (long)(bn + lr) * K + lc;

    for (int k0 = 0; k0 < K; k0 += 8) {
        float4 a4 = *(const float4*)(Ap + k0);
        float4 b4 = *(const float4*)(Bp + k0);
        __syncthreads();
        As[lc + 0][lr] = a4.x; As[lc + 1][lr] = a4.y;
        As[lc + 2][lr] = a4.z; As[lc + 3][lr] = a4.w;
        Bs[lc + 0][lr] = b4.x; Bs[lc + 1][lr] = b4.y;
        Bs[lc + 2][lr] = b4.z; Bs[lc + 3][lr] = b4.w;
        __syncthreads();
#pragma unroll
        for (int kk = 0; kk < 8; kk++) {
            float4 ra0 = *(const float4*)&As[kk][ty * 8];
            float4 ra1 = *(const float4*)&As[kk][ty * 8 + 4];
            float4 rb0 = *(const float4*)&Bs[kk][tx * 8];
            float4 rb1 = *(const float4*)&Bs[kk][tx * 8 + 4];
            float ra[8] = {ra0.x, ra0.y, ra0.z, ra0.w, ra1.x, ra1.y, ra1.z, ra1.w};
            float rb[8] = {rb0.x, rb0.y, rb0.z, rb0.w, rb1.x, rb1.y, rb1.z, rb1.w};
#pragma unroll
            for (int i = 0; i < 8; i++)
#pragma unroll
                for (int j = 0; j < 8; j++) acc[i][j] += ra[i] * rb[j];
        }
    }
#pragma unroll
    for (int i = 0; i < 8; i++)
#pragma unroll
        for (int j = 0; j < 8; j++)
            epi(z, bm + ty * 8 + i, bn + tx * 8 + j, acc[i][j]);
}

// epilogues
struct EpiQKV {
    const float* bias;
    __device__ void operator()(int, int m, int n, float acc) const {
        float vv = acc + __ldg(bias + n);
        int which = n >> 10;
        int rem = n & 1023;
        int h = rem >> 6, d = rem & 63;
        int b = m >> 10, t = m & 1023;
        float* dst = which == 0 ? g_q : (which == 1 ? g_k : g_v);
        dst[((((long)b * CH + h) * CN + t) << 6) + d] = vv;
    }
};

struct EpiScores {
    __device__ void operator()(int z, int i, int j, float acc) const {
        int dd = i - j;
        dd = dd < -64 ? -64 : (dd > 64 ? 64 : dd);
        float vv = acc * CSCALE + g_qr[((long)z * CN + i) * CVOCAB + (dd + 64)];
        g_sc[((long)z * CN + i) * CN + j] = vv;
    }
};

struct EpiOut {
    const float* bias;
    float* out;
    __device__ void operator()(int, int m, int n, float acc) const {
        out[(long)m * CDIM + n] = acc + __ldg(bias + n);
    }
};

// ---------------- qr[row, v] = dot(q[row,:], rel_k_emb[v,:]) ---------------
__global__ void __launch_bounds__(256)
qr_kernel(const float* __restrict__ relk)
{
    __shared__ float sembT[CDH][132]; // transposed [d][v], padded
    __shared__ float sq[32][CDH];
    const int row0 = blockIdx.x * 32;
    for (int idx = threadIdx.x; idx < CVOCAB * CDH; idx += 256) {
        int v = idx >> 6, d = idx & 63;
        sembT[d][v] = relk[idx];
    }
    for (int d = threadIdx.x; d < CDH; d += 256) {
        sembT[d][129] = 0.f; sembT[d][130] = 0.f; sembT[d][131] = 0.f;
    }
    for (int idx = threadIdx.x; idx < 32 * CDH; idx += 256)
        sq[idx >> 6][idx & 63] = g_q[(long)row0 * CDH + idx];
    __syncthreads();

    for (int t = threadIdx.x; t < 32 * 33; t += 256) {
        int r = t / 33, vg = t % 33;
        float4 acc = make_float4(0.f, 0.f, 0.f, 0.f);
#pragma unroll 16
        for (int d = 0; d < CDH; d++) {
            float qd = sq[r][d];
            float4 e = *(const float4*)&sembT[d][vg * 4];
            acc.x += qd * e.x; acc.y += qd * e.y;
            acc.z += qd * e.z; acc.w += qd * e.w;
        }
        int v0 = vg * 4;
        long base = (long)(row0 + r) * CVOCAB + v0;
        g_qr[base + 0] = acc.x;
        if (v0 + 1 < CVOCAB) g_qr[base + 1] = acc.y;
        if (v0 + 2 < CVOCAB) g_qr[base + 2] = acc.z;
        if (v0 + 3 < CVOCAB) g_qr[base + 3] = acc.w;
    }
}

// ---------------- top-k threshold (exact radix select) + masked softmax ----
__device__ __forceinline__ unsigned fkey(float f)
{
    unsigned u = __float_as_uint(f);
    return (u & 0x80000000u) ? ~u : (u | 0x80000000u);
}
__device__ __forceinline__ float fkeyinv(unsigned u)
{
    return __uint_as_float((u & 0x80000000u) ? (u & 0x7FFFFFFFu) : ~u);
}

__global__ void __launch_bounds__(256)
topk_softmax_kernel()
{
    const long row = blockIdx.x;
    float* S = g_sc + row * CN;
    __shared__ float sv[CN];
    __shared__ unsigned hist[256];
    __shared__ unsigned sc[256];
    __shared__ float red[256];
    __shared__ unsigned s_prefix, s_k;
    __shared__ float s_max, s_sum;
    const int tid = threadIdx.x;

    ((float4*)sv)[tid] = ((const float4*)S)[tid];
    if (tid == 0) { s_prefix = 0u; s_k = CTOPK; }
    __syncthreads();

    for (int pass = 0; pass < 4; pass++) {
        const int shift = 24 - pass * 8;
        hist[tid] = 0u;
        __syncthreads();
        const unsigned prefix = s_prefix;
        const unsigned k = s_k;
        for (int e = tid; e < CN; e += 256) {
            unsigned u = fkey(sv[e]);
            bool ok = (pass == 0) || (((u ^ prefix) >> (shift + 8)) == 0u);
            if (ok) atomicAdd(&hist[(u >> shift) & 255u], 1u);
        }
        __syncthreads();
        // inclusive suffix sum over 256 bins (Hillis-Steele)
        sc[tid] = hist[tid];
        for (int off = 1; off < 256; off <<= 1) {
            __syncthreads();
            unsigned add = (tid + off < 256) ? sc[tid + off] : 0u;
            __syncthreads();
            sc[tid] += add;
        }
        __syncthreads();
        unsigned above = (tid == 255) ? 0u : sc[tid + 1];
        if (sc[tid] >= k && above < k) {
            s_prefix = prefix | ((unsigned)tid << shift);
            s_k = k - above;
        }
        __syncthreads();
    }
    const float thr = fkeyinv(s_prefix);

    // row max (top element always kept, so max over all == max over kept)
    float lm = -3.4e38f;
    for (int e = tid; e < CN; e += 256) lm = fmaxf(lm, sv[e]);
    red[tid] = lm;
    for (int s = 128; s > 0; s >>= 1) {
        __syncthreads();
        if (tid < s) red[tid] = fmaxf(red[tid], red[tid + s]);
    }
    __syncthreads();
    if (tid == 0) s_max = red[0];
    __syncthreads();
    const float mx = s_max;

    float ls = 0.f;
    for (int e = tid; e < CN; e += 256) {
        float v = sv[e];
        if (!(v < thr)) ls += __expf(v - mx);
    }
    red[tid] = ls;
    for (int s = 128; s > 0; s >>= 1) {
        __syncthreads();
        if (tid < s) red[tid] += red[tid + s];
    }
    __syncthreads();
    if (tid == 0) s_sum = red[0];
    __syncthreads();
    const float inv = 1.f / s_sum;

    for (int e = tid; e < CN; e += 256) {
        float v = sv[e];
        S[e] = (v < thr) ? 0.f : __expf(v - mx) * inv;
    }
}

// ---------------- batched attn@V (NN): out[m,d] = sum_j attn[m,j]*vin[j,d] --
__global__ void __launch_bounds__(256)
attnv_kernel(const float* __restrict__ vin, float* __restrict__ vout,
             const float* __restrict__ alphas_raw, int order)
{
    const int z = blockIdx.y;
    const float* Amat = g_sc + (long)z * CN * CN;
    const float* Vin = vin + (long)z * CN * CDH;
    float* Vout = vout + (long)z * CN * CDH;
    float* Res = g_res + (long)z * CN * CDH;

    __shared__ float As[32][65];
    __shared__ float Bs[32][64];
    const int bm = blockIdx.x * 64;
    const int tid = threadIdx.x;
    const int ty = tid >> 4;
    const int tx = tid & 15;
    const int arow = tid >> 2;
    const int akc = (tid & 3) * 8;
    const int brow = tid >> 3;
    const int bc = (tid & 7) * 8;

    float acc[4][4];
#pragma unroll
    for (int i = 0; i < 4; i++)
#pragma unroll
        for (int j = 0; j < 4; j++) acc[i][j] = 0.f;

    for (int k0 = 0; k0 < CN; k0 += 32) {
        float4 a0 = *(const float4*)(Amat + (long)(bm + arow) * CN + k0 + akc);
        float4 a1 = *(const float4*)(Amat + (long)(bm + arow) * CN + k0 + akc + 4);
        float4 b0 = *(const float4*)(Vin + (long)(k0 + brow) * CDH + bc);
        float4 b1 = *(const float4*)(Vin + (long)(k0 + brow) * CDH + bc + 4);
        __syncthreads();
        As[akc + 0][arow] = a0.x; As[akc + 1][arow] = a0.y;
        As[akc + 2][arow] = a0.z; As[akc + 3][arow] = a0.w;
        As[akc + 4][arow] = a1.x; As[akc + 5][arow] = a1.y;
        As[akc + 6][arow] = a1.z; As[akc + 7][arow] = a1.w;
        *(float4*)&Bs[brow][bc] = b0;
        *(float4*)&Bs[brow][bc + 4] = b1;
        __syncthreads();
#pragma unroll
        for (int kk = 0; kk < 32; kk++) {
            float ra[4];
            float4 rb = *(const float4*)&Bs[kk][tx * 4];
#pragma unroll
            for (int i = 0; i < 4; i++) ra[i] = As[kk][ty * 4 + i];
            float rbv[4] = {rb.x, rb.y, rb.z, rb.w};
#pragma unroll
            for (int i = 0; i < 4; i++)
#pragma unroll
                for (int j = 0; j < 4; j++) acc[i][j] += ra[i] * rbv[j];
        }
    }

    const int h = z & 15;
    const float alpha = 1.f / (1.f + __expf(-__ldg(alphas_raw + order * CH + h)));
#pragma unroll
    for (int i = 0; i < 4; i++) {
#pragma unroll
        for (int j = 0; j < 4; j++) {
            int m = bm + ty * 4 + i;
            int n = tx * 4 + j;
            long idx = (long)m * CDH + n;
            Vout[idx] = acc[i][j];
            if (order > 0) Res[idx] += alpha * acc[i][j];
        }
    }
}

// ---------------- rel_v term: vc[i,:] += w(attn row) @ rel_v_emb; res=a0*vc -
__global__ void __launch_bounds__(128)
relv_kernel(const float* __restrict__ relv_emb, const float* __restrict__ alphas_raw)
{
    const long row = blockIdx.x; // z*1024 + i
    const int z = (int)(row >> 10);
    const int i = (int)(row & 1023);
    const int h = z & 15;
    const float* arow = g_sc + row * CN;
    __shared__ float sa[CN];
    __shared__ float w[CVOCAB];
    __shared__ float red[128];
    const int tid = threadIdx.x;

    for (int e = tid; e < CN; e += 128) sa[e] = arow[e];
    __syncthreads();

    float l0 = 0.f, l1 = 0.f;
    for (int e = tid; e < CN; e += 128) {
        float v = sa[e];
        if (e >= i + 64) l0 += v; // dist clipped to -64 -> bucket 0
        if (e <= i - 64) l1 += v; // dist clipped to +64 -> bucket 128
    }
    if (tid >= 1 && tid <= 127) {
        int j = i + 64 - tid;
        w[tid] = (j >= 0 && j < CN) ? sa[j] : 0.f;
    }
    red[tid] = l0;
    for (int s = 64; s > 0; s >>= 1) {
        __syncthreads();
        if (tid < s) red[tid] += red[tid + s];
    }
    __syncthreads();
    if (tid == 0) w[0] = red[0];
    __syncthreads();
    red[tid] = l1;
    for (int s = 64; s > 0; s >>= 1) {
        __syncthreads();
        if (tid < s) red[tid] += red[tid + s];
    }
    __syncthreads();
    if (tid == 0) w[128] = red[0];
    __syncthreads();

    if (tid < CDH) {
        const int d = tid;
        float acc = 0.f;
#pragma unroll 8
        for (int v = 0; v < CVOCAB; v++) acc += w[v] * __ldg(relv_emb + v * CDH + d);
        long idx = row * CDH + d;
        float nv = g_t0[idx] + acc;
        g_t0[idx] = nv;
        float alpha = 1.f / (1.f + __expf(-__ldg(alphas_raw + h))); // order 0
        g_res[idx] = alpha * nv;
    }
}

// ---------------- [BH][N][DH] -> [B][N][H*DH] -------------------------------
__global__ void __launch_bounds__(256)
transpose_res_kernel()
{
    long idx = (long)blockIdx.x * 256 + threadIdx.x; // over B*N*INNER
    int d = (int)(idx & 63);
    long t = idx >> 6;
    int h = (int)(t & 15);
    long t2 = t >> 4;
    int n = (int)(t2 & 1023);
    int b = (int)(t2 >> 10);
    g_resT[idx] = g_res[(((long)(b * CH + h) * CN + n) << 6) + d];
}

// ---------------- host launcher --------------------------------------------
extern "C" void kernel_launch(void* const* d_in, const int* in_sizes, int n_in,
                              void* d_out, int out_size)
{
    (void)in_sizes; (void)n_in; (void)out_size;
    const float* x      = (const float*)d_in[0];
    const float* Wqkv   = (const float*)d_in[1];
    const float* bqkv   = (const float*)d_in[2];
    const float* Wout   = (const float*)d_in[3];
    const float* bout   = (const float*)d_in[4];
    const float* relk   = (const float*)d_in[5];
    const float* relv   = (const float*)d_in[6];
    const float* alphas = (const float*)d_in[7];
    float* out = (float*)d_out;

    float *p_q, *p_k, *p_v, *p_t0, *p_t1, *p_resT;
    cudaGetSymbolAddress((void**)&p_q, g_q);
    cudaGetSymbolAddress((void**)&p_k, g_k);
    cudaGetSymbolAddress((void**)&p_v, g_v);
    cudaGetSymbolAddress((void**)&p_t0, g_t0);
    cudaGetSymbolAddress((void**)&p_t1, g_t1);
    cudaGetSymbolAddress((void**)&p_resT, g_resT);

    // 1) QKV projection: [4096,1024] @ [3072,1024]^T -> scatter heads
    sgemm_nt<<<dim3(3072 / 128, 4096 / 128, 1), 256>>>(
        x, Wqkv, 0L, 0L, 4096, 3072, 1024, EpiQKV{bqkv});

    // 2) q . rel_k_emb table
    qr_kernel<<<CROWS / 32, 256>>>(relk);

    // 3) scores = scale * q@k^T + qr gather (batched over 64 bh)
    sgemm_nt<<<dim3(CN / 128, CN / 128, CBH), 256>>>(
        p_q, p_k, (long)CN * CDH, (long)CN * CDH, CN, CN, CDH, EpiScores{});

    // 4) exact top-256 threshold + masked softmax, in place
    topk_softmax_kernel<<<CROWS, 256>>>();

    // 5) order 0: v1 = attn @ v
    attnv_kernel<<<dim3(CN / 64, CBH), 256>>>(p_v, p_t0, alphas, 0);
    // 5b) v1 += attn x rel_v ; res = a0 * v1
    relv_kernel<<<CROWS, 128>>>(relv, alphas);
    // 6) order 1: v2 = attn @ v1 ; res += a1 * v2
    attnv_kernel<<<dim3(CN / 64, CBH), 256>>>(p_t0, p_t1, alphas, 1);
    // 7) order 2: v3 = attn @ v2 ; res += a2 * v3
    attnv_kernel<<<dim3(CN / 64, CBH), 256>>>(p_t1, p_t0, alphas, 2);

    // 8) heads -> [B,N,INNER]
    transpose_res_kernel<<<(CB * CN * CINNER) / 256, 256>>>();

    // 9) output projection
    sgemm_nt<<<dim3(CDIM / 128, 4096 / 128, 1), 256>>>(
        p_resT, Wout, 0L, 0L, 4096, 1024, 1024, EpiOut{bout, out});
}

// round 3
// speedup vs baseline: 1.1073x; 1.1073x over previous
#include <cuda_runtime.h>
#include <math.h>

#define CB 4
#define CN 1024
#define CDIM 1024
#define CH 16
#define CDH 64
#define CINNER 1024
#define CVOCAB 129
#define CBH 64
#define CTOPK 256
#define CSCALE 0.125f
#define CROWS (CBH * CN) /* 65536 */

// ---------------- scratch (device globals; no allocation allowed) ----------
__device__ __align__(128) float g_q[CBH * CN * CDH];
__device__ __align__(128) float g_k[CBH * CN * CDH];
__device__ __align__(128) float g_v[CBH * CN * CDH];
__device__ __align__(128) float g_qr[(size_t)CROWS * CVOCAB];
__device__ __align__(128) float g_sc[(size_t)CBH * CN * CN]; // scores -> attn (256MB)
__device__ __align__(128) float g_rv[(size_t)CROWS * CDH];   // attn x rel_v term
__device__ __align__(128) float g_t0[CBH * CN * CDH];
__device__ __align__(128) float g_t1[CBH * CN * CDH];
__device__ __align__(128) float g_res[CBH * CN * CDH];
__device__ __align__(128) float g_resT[CB * CN * CINNER];

// ---------------- generic 128x128x8 NT SGEMM: C = A(MxK) * B(NxK)^T --------
template <class Epi>
__global__ void __launch_bounds__(256)
sgemm_nt(const float* __restrict__ A, const float* __restrict__ Bm,
         long sA, long sB, int M, int Nn, int K, Epi epi)
{
    __shared__ float As[8][128];
    __shared__ float Bs[8][128];
    const int z = blockIdx.z;
    A += (long)z * sA;
    Bm += (long)z * sB;
    const int bm = blockIdx.y * 128;
    const int bn = blockIdx.x * 128;
    const int tid = threadIdx.x;
    const int ty = tid >> 4;
    const int tx = tid & 15;
    const int lr = tid >> 1;
    const int lc = (tid & 1) * 4;
    float acc[8][8];
#pragma unroll
    for (int i = 0; i < 8; i++)
#pragma unroll
        for (int j = 0; j < 8; j++) acc[i][j] = 0.f;

    const float* Ap = A + (long)(bm + lr) * K + lc;
    const float* Bp = Bm + (long)(bn + lr) * K + lc;

    for (int k0 = 0; k0 < K; k0 += 8) {
        float4 a4 = *(const float4*)(Ap + k0);
        float4 b4 = *(const float4*)(Bp + k0);
        __syncthreads();
        As[lc + 0][lr] = a4.x; As[lc + 1][lr] = a4.y;
        As[lc + 2][lr] = a4.z; As[lc + 3][lr] = a4.w;
        Bs[lc + 0][lr] = b4.x; Bs[lc + 1][lr] = b4.y;
        Bs[lc + 2][lr] = b4.z; Bs[lc + 3][lr] = b4.w;
        __syncthreads();
#pragma unroll
        for (int kk = 0; kk < 8; kk++) {
            float4 ra0 = *(const float4*)&As[kk][ty * 8];
            float4 ra1 = *(const float4*)&As[kk][ty * 8 + 4];
            float4 rb0 = *(const float4*)&Bs[kk][tx * 8];
            float4 rb1 = *(const float4*)&Bs[kk][tx * 8 + 4];
            float ra[8] = {ra0.x, ra0.y, ra0.z, ra0.w, ra1.x, ra1.y, ra1.z, ra1.w};
            float rb[8] = {rb0.x, rb0.y, rb0.z, rb0.w, rb1.x, rb1.y, rb1.z, rb1.w};
#pragma unroll
            for (int i = 0; i < 8; i++)
#pragma unroll
                for (int j = 0; j < 8; j++) acc[i][j] += ra[i] * rb[j];
        }
    }
#pragma unroll
    for (int i = 0; i < 8; i++)
#pragma unroll
        for (int j = 0; j < 8; j++)
            epi(z, bm + ty * 8 + i, bn + tx * 8 + j, acc[i][j]);
}

// epilogues
struct EpiQKV {
    const float* bias;
    __device__ void operator()(int, int m, int n, float acc) const {
        float vv = acc + __ldg(bias + n);
        int which = n >> 10;
        int rem = n & 1023;
        int h = rem >> 6, d = rem & 63;
        int b = m >> 10, t = m & 1023;
        float* dst = which == 0 ? g_q : (which == 1 ? g_k : g_v);
        dst[((((long)b * CH + h) * CN + t) << 6) + d] = vv;
    }
};

struct EpiScores {
    __device__ void operator()(int z, int i, int j, float acc) const {
        int dd = i - j;
        dd = dd < -64 ? -64 : (dd > 64 ? 64 : dd);
        float vv = acc * CSCALE + g_qr[((long)z * CN + i) * CVOCAB + (dd + 64)];
        g_sc[((long)z * CN + i) * CN + j] = vv;
    }
};

struct EpiOut {
    const float* bias;
    float* out;
    __device__ void operator()(int, int m, int n, float acc) const {
        out[(long)m * CDIM + n] = acc + __ldg(bias + n);
    }
};

// ---------------- qr[row, v] = dot(q[row,:], rel_k_emb[v,:]) ---------------
__global__ void __launch_bounds__(256)
qr_kernel(const float* __restrict__ relk)
{
    __shared__ float sembT[CDH][132]; // transposed [d][v], padded
    __shared__ float sq[32][CDH];
    const int row0 = blockIdx.x * 32;
    for (int idx = threadIdx.x; idx < CVOCAB * CDH; idx += 256) {
        int v = idx >> 6, d = idx & 63;
        sembT[d][v] = relk[idx];
    }
    for (int d = threadIdx.x; d < CDH; d += 256) {
        sembT[d][129] = 0.f; sembT[d][130] = 0.f; sembT[d][131] = 0.f;
    }
    for (int idx = threadIdx.x; idx < 32 * CDH; idx += 256)
        sq[idx >> 6][idx & 63] = g_q[(long)row0 * CDH + idx];
    __syncthreads();

    for (int t = threadIdx.x; t < 32 * 33; t += 256) {
        int r = t / 33, vg = t % 33;
        float4 acc = make_float4(0.f, 0.f, 0.f, 0.f);
#pragma unroll 16
        for (int d = 0; d < CDH; d++) {
            float qd = sq[r][d];
            float4 e = *(const float4*)&sembT[d][vg * 4];
            acc.x += qd * e.x; acc.y += qd * e.y;
            acc.z += qd * e.z; acc.w += qd * e.w;
        }
        int v0 = vg * 4;
        long base = (long)(row0 + r) * CVOCAB + v0;
        g_qr[base + 0] = acc.x;
        if (v0 + 1 < CVOCAB) g_qr[base + 1] = acc.y;
        if (v0 + 2 < CVOCAB) g_qr[base + 2] = acc.z;
        if (v0 + 3 < CVOCAB) g_qr[base + 3] = acc.w;
    }
}

// ---------------- top-k threshold + masked softmax + rel_v weights ---------
__device__ __forceinline__ unsigned fkey(float f)
{
    unsigned u = __float_as_uint(f);
    return (u & 0x80000000u) ? ~u : (u | 0x80000000u);
}
__device__ __forceinline__ float fkeyinv(unsigned u)
{
    return __uint_as_float((u & 0x80000000u) ? (u & 0x7FFFFFFFu) : ~u);
}

__global__ void __launch_bounds__(256)
topk_softmax_relv_kernel(const float* __restrict__ relv_emb)
{
    const long row = blockIdx.x;
    const int i = (int)(row & 1023);
    float* S = g_sc + row * CN;
    __shared__ unsigned hist[256];
    __shared__ float red[16];
    __shared__ float w[132];
    __shared__ float rvp[4][CDH];
    __shared__ unsigned s_prefix, s_k;
    __shared__ float s_max, s_sum;
    const int tid = threadIdx.x;
    const int lane = tid & 31, wid = tid >> 5;

    float4 v4 = ((const float4*)S)[tid];
    float v[4] = {v4.x, v4.y, v4.z, v4.w};
    unsigned u[4];
#pragma unroll
    for (int j = 0; j < 4; j++) u[j] = fkey(v[j]);
    if (tid == 0) { s_prefix = 0u; s_k = CTOPK; }
    if (tid < 132) w[tid] = 0.f;

#pragma unroll
    for (int pass = 0; pass < 4; pass++) {
        const int shift = 24 - pass * 8;
        hist[tid] = 0u;
        __syncthreads();
        const unsigned prefix = s_prefix;
#pragma unroll
        for (int j = 0; j < 4; j++) {
            bool ok = (pass == 0) || (((u[j] ^ prefix) >> (shift + 8)) == 0u);
            unsigned bin = (u[j] >> shift) & 255u;
            unsigned key = ok ? bin : 0xFFFFFFFFu;
            unsigned mm = __match_any_sync(0xFFFFFFFFu, key);
            if (ok && lane == (unsigned)(__ffs(mm) - 1))
                atomicAdd(&hist[bin], (unsigned)__popc(mm));
        }
        __syncthreads();
        if (tid < 32) {
            unsigned h8[8]; unsigned t = 0;
#pragma unroll
            for (int j = 0; j < 8; j++) { h8[j] = hist[tid * 8 + j]; t += h8[j]; }
            unsigned s = t;
#pragma unroll
            for (int off = 1; off < 32; off <<= 1) {
                unsigned vv = __shfl_down_sync(0xFFFFFFFFu, s, off);
                if (tid + off < 32) s += vv;
            }
            unsigned prev = s - t;             // suffix count above this 8-bin group
            const unsigned pref = s_prefix;
            const unsigned kcur = s_k;
#pragma unroll
            for (int j = 7; j >= 0; j--) {
                unsigned cur = prev + h8[j];
                if (cur >= kcur && prev < kcur) {
                    s_prefix = pref | ((unsigned)(tid * 8 + j) << shift);
                    s_k = kcur - prev;
                }
                prev = cur;
            }
        }
        __syncthreads();
    }
    const float thr = fkeyinv(s_prefix);

    // row max (top element is always kept)
    float lm = fmaxf(fmaxf(v[0], v[1]), fmaxf(v[2], v[3]));
#pragma unroll
    for (int off = 16; off > 0; off >>= 1)
        lm = fmaxf(lm, __shfl_xor_sync(0xFFFFFFFFu, lm, off));
    if (lane == 0) red[wid] = lm;
    __syncthreads();
    if (tid == 0) {
        float m0 = red[0];
#pragma unroll
        for (int q = 1; q < 8; q++) m0 = fmaxf(m0, red[q]);
        s_max = m0;
    }
    __syncthreads();
    const float mx = s_max;

    float a[4];
    float ls = 0.f;
#pragma unroll
    for (int j = 0; j < 4; j++) {
        a[j] = (v[j] < thr) ? 0.f : __expf(v[j] - mx);
        ls += a[j];
    }
#pragma unroll
    for (int off = 16; off > 0; off >>= 1)
        ls += __shfl_xor_sync(0xFFFFFFFFu, ls, off);
    if (lane == 0) red[wid] = ls;
    __syncthreads();
    if (tid == 0) {
        float s0 = 0.f;
#pragma unroll
        for (int q = 0; q < 8; q++) s0 += red[q];
        s_sum = s0;
    }
    __syncthreads();
    const float inv = 1.f / s_sum;
#pragma unroll
    for (int j = 0; j < 4; j++) a[j] *= inv;
    ((float4*)S)[tid] = make_float4(a[0], a[1], a[2], a[3]);

    // rel_v bucket weights: bucket(e) = clip(i-e, -64, 64) + 64
    float l0 = 0.f, l1 = 0.f;
#pragma unroll
    for (int j = 0; j < 4; j++) {
        int e = tid * 4 + j;
        int del = i - e;
        if (del <= -64) l0 += a[j];
        else if (del >= 64) l1 += a[j];
        else w[del + 64] = a[j];   // unique writer per bucket
    }
#pragma unroll
    for (int off = 16; off > 0; off >>= 1) {
        l0 += __shfl_xor_sync(0xFFFFFFFFu, l0, off);
        l1 += __shfl_xor_sync(0xFFFFFFFFu, l1, off);
    }
    if (lane == 0) { red[wid] = l0; red[8 + wid] = l1; }
    __syncthreads();
    if (tid == 0) {
        float s0 = 0.f, s1 = 0.f;
#pragma unroll
        for (int q = 0; q < 8; q++) { s0 += red[q]; s1 += red[8 + q]; }
        w[0] = s0; w[128] = s1;
    }
    __syncthreads();

    // rv[d] = sum_t w[t] * rel_v_emb[t][d]
    {
        const int q = tid >> 6, d = tid & 63;
        const int tA = q * 33;
        const int tB = (tA + 33 < CVOCAB) ? tA + 33 : CVOCAB;
        float acc = 0.f;
        for (int t = tA; t < tB; t++)
            acc += w[t] * __ldg(relv_emb + t * CDH + d);
        rvp[q][d] = acc;
    }
    __syncthreads();
    if (tid < CDH)
        g_rv[row * CDH + tid] = rvp[0][tid] + rvp[1][tid] + rvp[2][tid] + rvp[3][tid];
}

// ---------------- batched attn@V (NN), 128x64 tile, k-tile 32 --------------
__global__ void __launch_bounds__(256)
attnv_kernel(const float* __restrict__ vin, float* __restrict__ vout,
             const float* __restrict__ alphas_raw, int order)
{
    const int z = blockIdx.y;
    const float* Amat = g_sc + (long)z * CN * CN;
    const float* Vin = vin + (long)z * CN * CDH;
    float* Vout = vout + (long)z * CN * CDH;
    float* Res = g_res + (long)z * CN * CDH;
    const float* Rv = g_rv + (long)z * CN * CDH;

    __shared__ float As[32][136];
    __shared__ float Bs[32][68];
    const int bm = blockIdx.x * 128;
    const int tid = threadIdx.x;
    const int ty = tid >> 4, tx = tid & 15;
    const int ar = tid >> 1, ak = (tid & 1) * 16;
    const int br = tid >> 3, bc = (tid & 7) * 8;

    float acc[8][4];
#pragma unroll
    for (int ii = 0; ii < 8; ii++)
#pragma unroll
        for (int jj = 0; jj < 4; jj++) acc[ii][jj] = 0.f;

    for (int k0 = 0; k0 < CN; k0 += 32) {
        float4 a4[4], b0, b1;
#pragma unroll
        for (int q = 0; q < 4; q++)
            a4[q] = *(const float4*)(Amat + (long)(bm + ar) * CN + k0 + ak + q * 4);
        b0 = *(const float4*)(Vin + (long)(k0 + br) * CDH + bc);
        b1 = *(const float4*)(Vin + (long)(k0 + br) * CDH + bc + 4);
        __syncthreads();
#pragma unroll
        for (int q = 0; q < 4; q++) {
            As[ak + q * 4 + 0][ar] = a4[q].x;
            As[ak + q * 4 + 1][ar] = a4[q].y;
            As[ak + q * 4 + 2][ar] = a4[q].z;
            As[ak + q * 4 + 3][ar] = a4[q].w;
        }
        *(float4*)&Bs[br][bc] = b0;
        *(float4*)&Bs[br][bc + 4] = b1;
        __syncthreads();
#pragma unroll
        for (int kk = 0; kk < 32; kk++) {
            float4 b = *(const float4*)&Bs[kk][tx * 4];
            float4 a0 = *(const float4*)&As[kk][ty * 8];
            float4 a1 = *(const float4*)&As[kk][ty * 8 + 4];
            float av[8] = {a0.x, a0.y, a0.z, a0.w, a1.x, a1.y, a1.z, a1.w};
            float bv[4] = {b.x, b.y, b.z, b.w};
#pragma unroll
            for (int ii = 0; ii < 8; ii++)
#pragma unroll
                for (int jj = 0; jj < 4; jj++) acc[ii][jj] += av[ii] * bv[jj];
        }
    }

    const int h = z & 15;
    const float alpha = 1.f / (1.f + __expf(-__ldg(alphas_raw + order * CH + h)));
#pragma unroll
    for (int ii = 0; ii < 8; ii++) {
#pragma unroll
        for (int jj = 0; jj < 4; jj++) {
            int m = bm + ty * 8 + ii;
            int n = tx * 4 + jj;
            long idx = (long)m * CDH + n;
            float val = acc[ii][jj];
            if (order == 0) {
                val += Rv[idx];
                Vout[idx] = val;
                Res[idx] = alpha * val;
            } else {
                Vout[idx] = val;
                Res[idx] += alpha * val;
            }
        }
    }
}

// ---------------- [BH][N][DH] -> [B][N][H*DH] -------------------------------
__global__ void __launch_bounds__(256)
transpose_res_kernel()
{
    long idx = (long)blockIdx.x * 256 + threadIdx.x; // over B*N*INNER
    int d = (int)(idx & 63);
    long t = idx >> 6;
    int h = (int)(t & 15);
    long t2 = t >> 4;
    int n = (int)(t2 & 1023);
    int b = (int)(t2 >> 10);
    g_resT[idx] = g_res[(((long)(b * CH + h) * CN + n) << 6) + d];
}

// ---------------- host launcher --------------------------------------------
extern "C" void kernel_launch(void* const* d_in, const int* in_sizes, int n_in,
                              void* d_out, int out_size)
{
    (void)in_sizes; (void)n_in; (void)out_size;
    const float* x      = (const float*)d_in[0];
    const float* Wqkv   = (const float*)d_in[1];
    const float* bqkv   = (const float*)d_in[2];
    const float* Wout   = (const float*)d_in[3];
    const float* bout   = (const float*)d_in[4];
    const float* relk   = (const float*)d_in[5];
    const float* relv   = (const float*)d_in[6];
    const float* alphas = (const float*)d_in[7];
    float* out = (float*)d_out;

    float *p_q, *p_k, *p_v, *p_t0, *p_t1, *p_resT;
    cudaGetSymbolAddress((void**)&p_q, g_q);
    cudaGetSymbolAddress((void**)&p_k, g_k);
    cudaGetSymbolAddress((void**)&p_v, g_v);
    cudaGetSymbolAddress((void**)&p_t0, g_t0);
    cudaGetSymbolAddress((void**)&p_t1, g_t1);
    cudaGetSymbolAddress((void**)&p_resT, g_resT);

    // 1) QKV projection: [4096,1024] @ [3072,1024]^T -> scatter heads
    sgemm_nt<<<dim3(3072 / 128, 4096 / 128, 1), 256>>>(
        x, Wqkv, 0L, 0L, 4096, 3072, 1024, EpiQKV{bqkv});

    // 2) q . rel_k_emb table
    qr_kernel<<<CROWS / 32, 256>>>(relk);

    // 3) scores = scale * q@k^T + qr gather (batched over 64 bh)
    sgemm_nt<<<dim3(CN / 128, CN / 128, CBH), 256>>>(
        p_q, p_k, (long)CN * CDH, (long)CN * CDH, CN, CN, CDH, EpiScores{});

    // 4) exact top-256 threshold + masked softmax + rel_v weights, in place
    topk_softmax_relv_kernel<<<CROWS, 256>>>(relv);

    // 5) order 0: t0 = attn @ v + rv ; res = a0 * t0
    attnv_kernel<<<dim3(CN / 128, CBH), 256>>>(p_v, p_t0, alphas, 0);
    // 6) order 1: t1 = attn @ t0 ; res += a1 * t1
    attnv_kernel<<<dim3(CN / 128, CBH), 256>>>(p_t0, p_t1, alphas, 1);
    // 7) order 2: t0' = attn @ t1 ; res += a2 * t0'
    attnv_kernel<<<dim3(CN / 128, CBH), 256>>>(p_t1, p_t0, alphas, 2);

    // 8) heads -> [B,N,INNER]
    transpose_res_kernel<<<(CB * CN * CINNER) / 256, 256>>>();

    // 9) output projection
    sgemm_nt<<<dim3(CDIM / 128, 4096 / 128, 1), 256>>>(
        p_resT, Wout, 0L, 0L, 4096, 1024, 1024, EpiOut{bout, out});
}

// round 5
// speedup vs baseline: 1.2627x; 1.1404x over previous
#include <cuda_runtime.h>
#include <cuda_bf16.h>
#include <math.h>

#define CB 4
#define CN 1024
#define CDIM 1024
#define CH 16
#define CDH 64
#define CINNER 1024
#define CVOCAB 129
#define CBH 64
#define CTOPK 256
#define CSCALE 0.125f
#define CROWS (CBH * CN) /* 65536 */

// ---------------- scratch (device globals; no allocation allowed) ----------
__device__ __align__(128) float g_q[CBH * CN * CDH];
__device__ __align__(128) float g_k[CBH * CN * CDH];
__device__ __align__(128) float g_v[CBH * CN * CDH];
__device__ __align__(128) float g_qr[(size_t)CROWS * CVOCAB];
__device__ __align__(128) float g_sc[(size_t)CBH * CN * CN]; // scores -> attn (256MB)
__device__ __align__(128) float g_rv[(size_t)CROWS * CDH];   // attn x rel_v term
__device__ __align__(128) float g_t0[CBH * CN * CDH];
__device__ __align__(128) float g_t1[CBH * CN * CDH];
__device__ __align__(128) float g_res[CBH * CN * CDH];
__device__ __align__(128) float g_resT[CB * CN * CINNER];

// ---------------- bf16 split helpers ---------------------------------------
__device__ __forceinline__ void split_bf16(float x, __nv_bfloat16& h, __nv_bfloat16& l)
{
    h = __float2bfloat16(x);
    l = __float2bfloat16(x - __bfloat162float(h));
}

#define MMA16816(c, a, b)                                                     \
    asm volatile(                                                             \
        "mma.sync.aligned.m16n8k16.row.col.f32.bf16.bf16.f32 "                \
        "{%0,%1,%2,%3},{%4,%5,%6,%7},{%8,%9},{%0,%1,%2,%3};"                  \
        : "+f"((c)[0]), "+f"((c)[1]), "+f"((c)[2]), "+f"((c)[3])              \
        : "r"((a)[0]), "r"((a)[1]), "r"((a)[2]), "r"((a)[3]),                 \
          "r"((b)[0]), "r"((b)[1]))

// ---------------- generic 128x128x8 NT SGEMM (fp32 exact) ------------------
template <class Epi>
__global__ void __launch_bounds__(256)
sgemm_nt(const float* __restrict__ A, const float* __restrict__ Bm,
         long sA, long sB, int M, int Nn, int K, Epi epi)
{
    __shared__ float As[8][128];
    __shared__ float Bs[8][128];
    const int z = blockIdx.z;
    A += (long)z * sA;
    Bm += (long)z * sB;
    const int bm = blockIdx.y * 128;
    const int bn = blockIdx.x * 128;
    const int tid = threadIdx.x;
    const int ty = tid >> 4;
    const int tx = tid & 15;
    const int lr = tid >> 1;
    const int lc = (tid & 1) * 4;
    float acc[8][8];
#pragma unroll
    for (int i = 0; i < 8; i++)
#pragma unroll
        for (int j = 0; j < 8; j++) acc[i][j] = 0.f;

    const float* Ap = A + (long)(bm + lr) * K + lc;
    const float* Bp = Bm + (long)(bn + lr) * K + lc;

    for (int k0 = 0; k0 < K; k0 += 8) {
        float4 a4 = *(const float4*)(Ap + k0);
        float4 b4 = *(const float4*)(Bp + k0);
        __syncthreads();
        As[lc + 0][lr] = a4.x; As[lc + 1][lr] = a4.y;
        As[lc + 2][lr] = a4.z; As[lc + 3][lr] = a4.w;
        Bs[lc + 0][lr] = b4.x; Bs[lc + 1][lr] = b4.y;
        Bs[lc + 2][lr] = b4.z; Bs[lc + 3][lr] = b4.w;
        __syncthreads();
#pragma unroll
        for (int kk = 0; kk < 8; kk++) {
            float4 ra0 = *(const float4*)&As[kk][ty * 8];
            float4 ra1 = *(const float4*)&As[kk][ty * 8 + 4];
            float4 rb0 = *(const float4*)&Bs[kk][tx * 8];
            float4 rb1 = *(const float4*)&Bs[kk][tx * 8 + 4];
            float ra[8] = {ra0.x, ra0.y, ra0.z, ra0.w, ra1.x, ra1.y, ra1.z, ra1.w};
            float rb[8] = {rb0.x, rb0.y, rb0.z, rb0.w, rb1.x, rb1.y, rb1.z, rb1.w};
#pragma unroll
            for (int i = 0; i < 8; i++)
#pragma unroll
                for (int j = 0; j < 8; j++) acc[i][j] += ra[i] * rb[j];
        }
    }
#pragma unroll
    for (int i = 0; i < 8; i++)
#pragma unroll
        for (int j = 0; j < 8; j++)
            epi(z, bm + ty * 8 + i, bn + tx * 8 + j, acc[i][j]);
}

// epilogues
struct EpiQKV {
    const float* bias;
    __device__ void operator()(int, int m, int n, float acc) const {
        float vv = acc + __ldg(bias + n);
        int which = n >> 10;
        int rem = n & 1023;
        int h = rem >> 6, d = rem & 63;
        int b = m >> 10, t = m & 1023;
        float* dst = which == 0 ? g_q : (which == 1 ? g_k : g_v);
        dst[((((long)b * CH + h) * CN + t) << 6) + d] = vv;
    }
};

struct EpiScores {
    __device__ void operator()(int z, int i, int j, float acc) const {
        int dd = i - j;
        dd = dd < -64 ? -64 : (dd > 64 ? 64 : dd);
        float vv = acc * CSCALE + g_qr[((long)z * CN + i) * CVOCAB + (dd + 64)];
        g_sc[((long)z * CN + i) * CN + j] = vv;
    }
};

struct EpiOut {
    const float* bias;
    float* out;
    __device__ void operator()(int, int m, int n, float acc) const {
        out[(long)m * CDIM + n] = acc + __ldg(bias + n);
    }
};

// ---------------- split-bf16 tensor-core NT GEMM: C = A(MxK) @ B(NxK)^T ----
// block 128x128, 8 warps (4m x 2n), warp tile 32x64, k-chunk 32
template <class Epi>
__global__ void __launch_bounds__(256)
bgemm_nt_mma(const float* __restrict__ A, const float* __restrict__ Bm,
             long sA, long sB, int M, int Nn, int K, Epi epi)
{
    __shared__ __nv_bfloat16 sAh[128][40], sAl[128][40];
    __shared__ __nv_bfloat16 sBh[128][40], sBl[128][40];
    const int z = blockIdx.z;
    A += (long)z * sA;
    Bm += (long)z * sB;
    const int bm = blockIdx.y * 128;
    const int bn = blockIdx.x * 128;
    const int tid = threadIdx.x;
    const int w = tid >> 5, lane = tid & 31;
    const int wm = w & 3, wn = w >> 2;
    const int g = lane >> 2, t = lane & 3;
    const int lr = tid >> 1, lq = (tid & 1) * 16;

    float c[2][8][4];
#pragma unroll
    for (int mt = 0; mt < 2; mt++)
#pragma unroll
        for (int nt = 0; nt < 8; nt++)
#pragma unroll
            for (int e = 0; e < 4; e++) c[mt][nt][e] = 0.f;

    const float* Ap = A + (long)(bm + lr) * K + lq;
    const float* Bp = Bm + (long)(bn + lr) * K + lq;

    for (int k0 = 0; k0 < K; k0 += 32) {
        float4 a4[4], b4[4];
#pragma unroll
        for (int j = 0; j < 4; j++) {
            a4[j] = *(const float4*)(Ap + k0 + j * 4);
            b4[j] = *(const float4*)(Bp + k0 + j * 4);
        }
        __syncthreads();
#pragma unroll
        for (int j = 0; j < 4; j++) {
            float xa[4] = {a4[j].x, a4[j].y, a4[j].z, a4[j].w};
            float xb[4] = {b4[j].x, b4[j].y, b4[j].z, b4[j].w};
#pragma unroll
            for (int e = 0; e < 4; e += 2) {
                __nv_bfloat16 h0, l0, h1, l1;
                split_bf16(xa[e], h0, l0); split_bf16(xa[e + 1], h1, l1);
                *(__nv_bfloat162*)&sAh[lr][lq + j * 4 + e] = __nv_bfloat162(h0, h1);
                *(__nv_bfloat162*)&sAl[lr][lq + j * 4 + e] = __nv_bfloat162(l0, l1);
                split_bf16(xb[e], h0, l0); split_bf16(xb[e + 1], h1, l1);
                *(__nv_bfloat162*)&sBh[lr][lq + j * 4 + e] = __nv_bfloat162(h0, h1);
                *(__nv_bfloat162*)&sBl[lr][lq + j * 4 + e] = __nv_bfloat162(l0, l1);
            }
        }
        __syncthreads();
#pragma unroll
        for (int ks = 0; ks < 32; ks += 16) {
            unsigned Ah[2][4], Al[2][4], Bh[8][2], Bl[8][2];
#pragma unroll
            for (int mt = 0; mt < 2; mt++) {
                int r0 = wm * 32 + mt * 16 + g;
                Ah[mt][0] = *(const unsigned*)&sAh[r0][ks + 2 * t];
                Ah[mt][1] = *(const unsigned*)&sAh[r0 + 8][ks + 2 * t];
                Ah[mt][2] = *(const unsigned*)&sAh[r0][ks + 2 * t + 8];
                Ah[mt][3] = *(const unsigned*)&sAh[r0 + 8][ks + 2 * t + 8];
                Al[mt][0] = *(const unsigned*)&sAl[r0][ks + 2 * t];
                Al[mt][1] = *(const unsigned*)&sAl[r0 + 8][ks + 2 * t];
                Al[mt][2] = *(const unsigned*)&sAl[r0][ks + 2 * t + 8];
                Al[mt][3] = *(const unsigned*)&sAl[r0 + 8][ks + 2 * t + 8];
            }
#pragma unroll
            for (int nt = 0; nt < 8; nt++) {
                int n0 = wn * 64 + nt * 8 + g;
                Bh[nt][0] = *(const unsigned*)&sBh[n0][ks + 2 * t];
                Bh[nt][1] = *(const unsigned*)&sBh[n0][ks + 2 * t + 8];
                Bl[nt][0] = *(const unsigned*)&sBl[n0][ks + 2 * t];
                Bl[nt][1] = *(const unsigned*)&sBl[n0][ks + 2 * t + 8];
            }
#pragma unroll
            for (int mt = 0; mt < 2; mt++)
#pragma unroll
                for (int nt = 0; nt < 8; nt++) {
                    MMA16816(c[mt][nt], Ah[mt], Bh[nt]);
                    MMA16816(c[mt][nt], Al[mt], Bh[nt]);
                    MMA16816(c[mt][nt], Ah[mt], Bl[nt]);
                }
        }
    }
#pragma unroll
    for (int mt = 0; mt < 2; mt++)
#pragma unroll
        for (int nt = 0; nt < 8; nt++) {
            int row = bm + wm * 32 + mt * 16 + g;
            int col = bn + wn * 64 + nt * 8 + 2 * t;
            epi(z, row, col, c[mt][nt][0]);
            epi(z, row, col + 1, c[mt][nt][1]);
            epi(z, row + 8, col, c[mt][nt][2]);
            epi(z, row + 8, col + 1, c[mt][nt][3]);
        }
}

// ---------------- split-bf16 attn@V (NN): C[1024,64] = attn @ vin ----------
// block: 128 m-rows x full n=64; 8 warps (4m x 2n), warp tile 32m x 32n
__global__ void __launch_bounds__(256)
attnv_mma(const float* __restrict__ vin, float* __restrict__ vout,
          const float* __restrict__ alphas_raw, int order)
{
    __shared__ __nv_bfloat16 sAh[128][40], sAl[128][40];
    __shared__ __nv_bfloat16 sBh[64][40], sBl[64][40];
    const int z = blockIdx.y;
    const float* Amat = g_sc + (long)z * CN * CN;
    const float* Vin = vin + (long)z * CN * CDH;
    float* Vout = vout + (long)z * CN * CDH;
    float* Res = g_res + (long)z * CN * CDH;
    const float* Rv = g_rv + (long)z * CN * CDH;

    const int bm = blockIdx.x * 128;
    const int tid = threadIdx.x;
    const int w = tid >> 5, lane = tid & 31;
    const int wm = w & 3, wn = w >> 2;
    const int g = lane >> 2, t = lane & 3;
    const int lr = tid >> 1, lq = (tid & 1) * 16;
    const int vn = tid & 63, kp2 = (tid >> 6) * 2;

    float c[2][4][4];
#pragma unroll
    for (int mt = 0; mt < 2; mt++)
#pragma unroll
        for (int nt = 0; nt < 4; nt++)
#pragma unroll
            for (int e = 0; e < 4; e++) c[mt][nt][e] = 0.f;

    for (int k0 = 0; k0 < CN; k0 += 32) {
        float4 a4[4];
#pragma unroll
        for (int j = 0; j < 4; j++)
            a4[j] = *(const float4*)(Amat + (long)(bm + lr) * CN + k0 + lq + j * 4);
        float vx0[4], vx1[4];
#pragma unroll
        for (int p = 0; p < 4; p++) {
            int kg = k0 + p * 8 + kp2;
            vx0[p] = Vin[(long)kg * CDH + vn];
            vx1[p] = Vin[(long)(kg + 1) * CDH + vn];
        }
        __syncthreads();
#pragma unroll
        for (int j = 0; j < 4; j++) {
            float xa[4] = {a4[j].x, a4[j].y, a4[j].z, a4[j].w};
#pragma unroll
            for (int e = 0; e < 4; e += 2) {
                __nv_bfloat16 h0, l0, h1, l1;
                split_bf16(xa[e], h0, l0); split_bf16(xa[e + 1], h1, l1);
                *(__nv_bfloat162*)&sAh[lr][lq + j * 4 + e] = __nv_bfloat162(h0, h1);
                *(__nv_bfloat162*)&sAl[lr][lq + j * 4 + e] = __nv_bfloat162(l0, l1);
            }
        }
#pragma unroll
        for (int p = 0; p < 4; p++) {
            __nv_bfloat16 h0, l0, h1, l1;
            split_bf16(vx0[p], h0, l0); split_bf16(vx1[p], h1, l1);
            *(__nv_bfloat162*)&sBh[vn][p * 8 + kp2] = __nv_bfloat162(h0, h1);
            *(__nv_bfloat162*)&sBl[vn][p * 8 + kp2] = __nv_bfloat162(l0, l1);
        }
        __syncthreads();
#pragma unroll
        for (int ks = 0; ks < 32; ks += 16) {
            unsigned Ah[2][4], Al[2][4], Bh[4][2], Bl[4][2];
#pragma unroll
            for (int mt = 0; mt < 2; mt++) {
                int r0 = wm * 32 + mt * 16 + g;
                Ah[mt][0] = *(const unsigned*)&sAh[r0][ks + 2 * t];
                Ah[mt][1] = *(const unsigned*)&sAh[r0 + 8][ks + 2 * t];
                Ah[mt][2] = *(const unsigned*)&sAh[r0][ks + 2 * t + 8];
                Ah[mt][3] = *(const unsigned*)&sAh[r0 + 8][ks + 2 * t + 8];
                Al[mt][0] = *(const unsigned*)&sAl[r0][ks + 2 * t];
                Al[mt][1] = *(const unsigned*)&sAl[r0 + 8][ks + 2 * t];
                Al[mt][2] = *(const unsigned*)&sAl[r0][ks + 2 * t + 8];
                Al[mt][3] = *(const unsigned*)&sAl[r0 + 8][ks + 2 * t + 8];
            }
#pragma unroll
            for (int nt = 0; nt < 4; nt++) {
                int n0 = wn * 32 + nt * 8 + g;
                Bh[nt][0] = *(const unsigned*)&sBh[n0][ks + 2 * t];
                Bh[nt][1] = *(const unsigned*)&sBh[n0][ks + 2 * t + 8];
                Bl[nt][0] = *(const unsigned*)&sBl[n0][ks + 2 * t];
                Bl[nt][1] = *(const unsigned*)&sBl[n0][ks + 2 * t + 8];
            }
#pragma unroll
            for (int mt = 0; mt < 2; mt++)
#pragma unroll
                for (int nt = 0; nt < 4; nt++) {
                    MMA16816(c[mt][nt], Ah[mt], Bh[nt]);
                    MMA16816(c[mt][nt], Al[mt], Bh[nt]);
                    MMA16816(c[mt][nt], Ah[mt], Bl[nt]);
                }
        }
    }

    const int h = z & 15;
    const float alpha = 1.f / (1.f + __expf(-__ldg(alphas_raw + order * CH + h)));
#pragma unroll
    for (int mt = 0; mt < 2; mt++)
#pragma unroll
        for (int nt = 0; nt < 4; nt++)
#pragma unroll
            for (int e = 0; e < 4; e++) {
                int row = bm + wm * 32 + mt * 16 + g + (e >= 2 ? 8 : 0);
                int col = wn * 32 + nt * 8 + 2 * t + (e & 1);
                long idx = (long)row * CDH + col;
                float val = c[mt][nt][e];
                if (order == 0) {
                    val += Rv[idx];
                    Vout[idx] = val;
                    Res[idx] = alpha * val;
                } else {
                    Vout[idx] = val;
                    Res[idx] += alpha * val;
                }
            }
}

// ---------------- qr[row, v] = dot(q[row,:], rel_k_emb[v,:]) ---------------
__global__ void __launch_bounds__(256)
qr_kernel(const float* __restrict__ relk)
{
    __shared__ float sembT[CDH][132]; // transposed [d][v], padded
    __shared__ float sq[32][CDH];
    const int row0 = blockIdx.x * 32;
    for (int idx = threadIdx.x; idx < CVOCAB * CDH; idx += 256) {
        int v = idx >> 6, d = idx & 63;
        sembT[d][v] = relk[idx];
    }
    for (int d = threadIdx.x; d < CDH; d += 256) {
        sembT[d][129] = 0.f; sembT[d][130] = 0.f; sembT[d][131] = 0.f;
    }
    for (int idx = threadIdx.x; idx < 32 * CDH; idx += 256)
        sq[idx >> 6][idx & 63] = g_q[(long)row0 * CDH + idx];
    __syncthreads();

    for (int t = threadIdx.x; t < 32 * 33; t += 256) {
        int r = t / 33, vg = t % 33;
        float4 acc = make_float4(0.f, 0.f, 0.f, 0.f);
#pragma unroll 16
        for (int d = 0; d < CDH; d++) {
            float qd = sq[r][d];
            float4 e = *(const float4*)&sembT[d][vg * 4];
            acc.x += qd * e.x; acc.y += qd * e.y;
            acc.z += qd * e.z; acc.w += qd * e.w;
        }
        int v0 = vg * 4;
        long base = (long)(row0 + r) * CVOCAB + v0;
        g_qr[base + 0] = acc.x;
        if (v0 + 1 < CVOCAB) g_qr[base + 1] = acc.y;
        if (v0 + 2 < CVOCAB) g_qr[base + 2] = acc.z;
        if (v0 + 3 < CVOCAB) g_qr[base + 3] = acc.w;
    }
}

// ---------------- top-k threshold + masked softmax + rel_v weights ---------
__device__ __forceinline__ unsigned fkey(float f)
{
    unsigned u = __float_as_uint(f);
    return (u & 0x80000000u) ? ~u : (u | 0x80000000u);
}
__device__ __forceinline__ float fkeyinv(unsigned u)
{
    return __uint_as_float((u & 0x80000000u) ? (u & 0x7FFFFFFFu) : ~u);
}

__global__ void __launch_bounds__(256)
topk_softmax_relv_kernel(const float* __restrict__ relv_emb)
{
    const long row = blockIdx.x;
    const int i = (int)(row & 1023);
    float* S = g_sc + row * CN;
    __shared__ unsigned hist[256];
    __shared__ float red[16];
    __shared__ float w[132];
    __shared__ float rvp[4][CDH];
    __shared__ unsigned s_prefix, s_k;
    __shared__ float s_max, s_sum;
    const int tid = threadIdx.x;
    const int lane = tid & 31, wid = tid >> 5;

    float4 v4 = ((const float4*)S)[tid];
    float v[4] = {v4.x, v4.y, v4.z, v4.w};
    unsigned u[4];
#pragma unroll
    for (int j = 0; j < 4; j++) u[j] = fkey(v[j]);
    if (tid == 0) { s_prefix = 0u; s_k = CTOPK; }
    if (tid < 132) w[tid] = 0.f;

#pragma unroll
    for (int pass = 0; pass < 4; pass++) {
        const int shift = 24 - pass * 8;
        hist[tid] = 0u;
        __syncthreads();
        const unsigned prefix = s_prefix;
#pragma unroll
        for (int j = 0; j < 4; j++) {
            bool ok = (pass == 0) || (((u[j] ^ prefix) >> (shift + 8)) == 0u);
            unsigned bin = (u[j] >> shift) & 255u;
            unsigned key = ok ? bin : 0xFFFFFFFFu;
            unsigned mm = __match_any_sync(0xFFFFFFFFu, key);
            if (ok && lane == (unsigned)(__ffs(mm) - 1))
                atomicAdd(&hist[bin], (unsigned)__popc(mm));
        }
        __syncthreads();
        if (tid < 32) {
            unsigned h8[8]; unsigned t = 0;
#pragma unroll
            for (int j = 0; j < 8; j++) { h8[j] = hist[tid * 8 + j]; t += h8[j]; }
            unsigned s = t;
#pragma unroll
            for (int off = 1; off < 32; off <<= 1) {
                unsigned vv = __shfl_down_sync(0xFFFFFFFFu, s, off);
                if (tid + off < 32) s += vv;
            }
            unsigned prev = s - t;             // suffix count above this 8-bin group
            const unsigned pref = s_prefix;
            const unsigned kcur = s_k;
#pragma unroll
            for (int j = 7; j >= 0; j--) {
                unsigned cur = prev + h8[j];
                if (cur >= kcur && prev < kcur) {
                    s_prefix = pref | ((unsigned)(tid * 8 + j) << shift);
                    s_k = kcur - prev;
                }
                prev = cur;
            }
        }
        __syncthreads();
    }
    const float thr = fkeyinv(s_prefix);

    // row max (top element is always kept)
    float lm = fmaxf(fmaxf(v[0], v[1]), fmaxf(v[2], v[3]));
#pragma unroll
    for (int off = 16; off > 0; off >>= 1)
        lm = fmaxf(lm, __shfl_xor_sync(0xFFFFFFFFu, lm, off));
    if (lane == 0) red[wid] = lm;
    __syncthreads();
    if (tid == 0) {
        float m0 = red[0];
#pragma unroll
        for (int q = 1; q < 8; q++) m0 = fmaxf(m0, red[q]);
        s_max = m0;
    }
    __syncthreads();
    const float mx = s_max;

    float a[4];
    float ls = 0.f;
#pragma unroll
    for (int j = 0; j < 4; j++) {
        a[j] = (v[j] < thr) ? 0.f : __expf(v[j] - mx);
        ls += a[j];
    }
#pragma unroll
    for (int off = 16; off > 0; off >>= 1)
        ls += __shfl_xor_sync(0xFFFFFFFFu, ls, off);
    if (lane == 0) red[wid] = ls;
    __syncthreads();
    if (tid == 0) {
        float s0 = 0.f;
#pragma unroll
        for (int q = 0; q < 8; q++) s0 += red[q];
        s_sum = s0;
    }
    __syncthreads();
    const float inv = 1.f / s_sum;
#pragma unroll
    for (int j = 0; j < 4; j++) a[j] *= inv;
    ((float4*)S)[tid] = make_float4(a[0], a[1], a[2], a[3]);

    // rel_v bucket weights: bucket(e) = clip(i-e, -64, 64) + 64
    float l0 = 0.f, l1 = 0.f;
#pragma unroll
    for (int j = 0; j < 4; j++) {
        int e = tid * 4 + j;
        int del = i - e;
        if (del <= -64) l0 += a[j];
        else if (del >= 64) l1 += a[j];
        else w[del + 64] = a[j];   // unique writer per bucket
    }
#pragma unroll
    for (int off = 16; off > 0; off >>= 1) {
        l0 += __shfl_xor_sync(0xFFFFFFFFu, l0, off);
        l1 += __shfl_xor_sync(0xFFFFFFFFu, l1, off);
    }
    if (lane == 0) { red[wid] = l0; red[8 + wid] = l1; }
    __syncthreads();
    if (tid == 0) {
        float s0 = 0.f, s1 = 0.f;
#pragma unroll
        for (int q = 0; q < 8; q++) { s0 += red[q]; s1 += red[8 + q]; }
        w[0] = s0; w[128] = s1;
    }
    __syncthreads();

    // rv[d] = sum_t w[t] * rel_v_emb[t][d]
    {
        const int q = tid >> 6, d = tid & 63;
        const int tA = q * 33;
        const int tB = (tA + 33 < CVOCAB) ? tA + 33 : CVOCAB;
        float acc = 0.f;
        for (int t = tA; t < tB; t++)
            acc += w[t] * __ldg(relv_emb + t * CDH + d);
        rvp[q][d] = acc;
    }
    __syncthreads();
    if (tid < CDH)
        g_rv[row * CDH + tid] = rvp[0][tid] + rvp[1][tid] + rvp[2][tid] + rvp[3][tid];
}

// ---------------- [BH][N][DH] -> [B][N][H*DH] -------------------------------
__global__ void __launch_bounds__(256)
transpose_res_kernel()
{
    long idx = (long)blockIdx.x * 256 + threadIdx.x; // over B*N*INNER
    int d = (int)(idx & 63);
    long t = idx >> 6;
    int h = (int)(t & 15);
    long t2 = t >> 4;
    int n = (int)(t2 & 1023);
    int b = (int)(t2 >> 10);
    g_resT[idx] = g_res[(((long)(b * CH + h) * CN + n) << 6) + d];
}

// ---------------- host launcher --------------------------------------------
extern "C" void kernel_launch(void* const* d_in, const int* in_sizes, int n_in,
                              void* d_out, int out_size)
{
    (void)in_sizes; (void)n_in; (void)out_size;
    const float* x      = (const float*)d_in[0];
    const float* Wqkv   = (const float*)d_in[1];
    const float* bqkv   = (const float*)d_in[2];
    const float* Wout   = (const float*)d_in[3];
    const float* bout   = (const float*)d_in[4];
    const float* relk   = (const float*)d_in[5];
    const float* relv   = (const float*)d_in[6];
    const float* alphas = (const float*)d_in[7];
    float* out = (float*)d_out;

    float *p_q, *p_k, *p_v, *p_t0, *p_t1, *p_resT;
    cudaGetSymbolAddress((void**)&p_q, g_q);
    cudaGetSymbolAddress((void**)&p_k, g_k);
    cudaGetSymbolAddress((void**)&p_v, g_v);
    cudaGetSymbolAddress((void**)&p_t0, g_t0);
    cudaGetSymbolAddress((void**)&p_t1, g_t1);
    cudaGetSymbolAddress((void**)&p_resT, g_resT);

    // 1) QKV projection (fp32 exact: feeds the top-k threshold)
    sgemm_nt<<<dim3(3072 / 128, 4096 / 128, 1), 256>>>(
        x, Wqkv, 0L, 0L, 4096, 3072, 1024, EpiQKV{bqkv});

    // 2) q . rel_k_emb table
    qr_kernel<<<CROWS / 32, 256>>>(relk);

    // 3) scores = scale * q@k^T + qr gather (fp32 exact, batched over 64 bh)
    sgemm_nt<<<dim3(CN / 128, CN / 128, CBH), 256>>>(
        p_q, p_k, (long)CN * CDH, (long)CN * CDH, CN, CN, CDH, EpiScores{});

    // 4) exact top-256 threshold + masked softmax + rel_v weights, in place
    topk_softmax_relv_kernel<<<CROWS, 256>>>(relv);

    // 5-7) attn @ V chain on tensor cores (split-bf16)
    attnv_mma<<<dim3(CN / 128, CBH), 256>>>(p_v, p_t0, alphas, 0);
    attnv_mma<<<dim3(CN / 128, CBH), 256>>>(p_t0, p_t1, alphas, 1);
    attnv_mma<<<dim3(CN / 128, CBH), 256>>>(p_t1, p_t0, alphas, 2);

    // 8) heads -> [B,N,INNER]
    transpose_res_kernel<<<(CB * CN * CINNER) / 256, 256>>>();

    // 9) output projection on tensor cores (split-bf16)
    bgemm_nt_mma<<<dim3(CDIM / 128, 4096 / 128, 1), 256>>>(
        p_resT, Wout, 0L, 0L, 4096, 1024, 1024, EpiOut{bout, out});
}

// round 13
// speedup vs baseline: 1.2872x; 1.0194x over previous
#include <cuda_runtime.h>
#include <cuda_bf16.h>
#include <math.h>

#define CB 4
#define CN 1024
#define CDIM 1024
#define CH 16
#define CDH 64
#define CINNER 1024
#define CVOCAB 129
#define CBH 64
#define CTOPK 256
#define CSCALE 0.125f
#define CROWS (CBH * CN) /* 65536 */
#define CWSTR 132        /* g_w row stride */

// ---------------- scratch (device globals; no allocation allowed) ----------
__device__ __align__(128) float g_q[CBH * CN * CDH];
__device__ __align__(128) float g_k[CBH * CN * CDH];
__device__ __align__(128) float g_v[CBH * CN * CDH];
__device__ __align__(128) float g_qr[(size_t)CROWS * CVOCAB];
__device__ __align__(128) float g_sc[(size_t)CBH * CN * CN]; // scores -> attn (256MB)
__device__ __align__(128) float g_w[(size_t)CROWS * CWSTR];  // rel_v bucket weights
__device__ __align__(128) float g_t0[CBH * CN * CDH];
__device__ __align__(128) float g_t1[CBH * CN * CDH];
__device__ __align__(128) float g_res[CBH * CN * CDH];

// ---------------- bf16 split helpers ---------------------------------------
__device__ __forceinline__ void split_bf16(float x, __nv_bfloat16& h, __nv_bfloat16& l)
{
    h = __float2bfloat16(x);
    l = __float2bfloat16(x - __bfloat162float(h));
}

#define MMA16816(c, a, b)                                                     \
    asm volatile(                                                             \
        "mma.sync.aligned.m16n8k16.row.col.f32.bf16.bf16.f32 "                \
        "{%0,%1,%2,%3},{%4,%5,%6,%7},{%8,%9},{%0,%1,%2,%3};"                  \
        : "+f"((c)[0]), "+f"((c)[1]), "+f"((c)[2]), "+f"((c)[3])              \
        : "r"((a)[0]), "r"((a)[1]), "r"((a)[2]), "r"((a)[3]),                 \
          "r"((b)[0]), "r"((b)[1]))

// ---------------- generic 128x128x8 NT SGEMM (fp32 exact) ------------------
template <class Epi>
__global__ void __launch_bounds__(256)
sgemm_nt(const float* __restrict__ A, const float* __restrict__ Bm,
         long sA, long sB, int M, int Nn, int K, Epi epi)
{
    __shared__ float As[8][128];
    __shared__ float Bs[8][128];
    const int z = blockIdx.z;
    A += (long)z * sA;
    Bm += (long)z * sB;
    const int bm = blockIdx.y * 128;
    const int bn = blockIdx.x * 128;
    const int tid = threadIdx.x;
    const int ty = tid >> 4;
    const int tx = tid & 15;
    const int lr = tid >> 1;
    const int lc = (tid & 1) * 4;
    float acc[8][8];
#pragma unroll
    for (int i = 0; i < 8; i++)
#pragma unroll
        for (int j = 0; j < 8; j++) acc[i][j] = 0.f;

    const float* Ap = A + (long)(bm + lr) * K + lc;
    const float* Bp = Bm + (long)(bn + lr) * K + lc;

    for (int k0 = 0; k0 < K; k0 += 8) {
        float4 a4 = *(const float4*)(Ap + k0);
        float4 b4 = *(const float4*)(Bp + k0);
        __syncthreads();
        As[lc + 0][lr] = a4.x; As[lc + 1][lr] = a4.y;
        As[lc + 2][lr] = a4.z; As[lc + 3][lr] = a4.w;
        Bs[lc + 0][lr] = b4.x; Bs[lc + 1][lr] = b4.y;
        Bs[lc + 2][lr] = b4.z; Bs[lc + 3][lr] = b4.w;
        __syncthreads();
#pragma unroll
        for (int kk = 0; kk < 8; kk++) {
            float4 ra0 = *(const float4*)&As[kk][ty * 8];
            float4 ra1 = *(const float4*)&As[kk][ty * 8 + 4];
            float4 rb0 = *(const float4*)&Bs[kk][tx * 8];
            float4 rb1 = *(const float4*)&Bs[kk][tx * 8 + 4];
            float ra[8] = {ra0.x, ra0.y, ra0.z, ra0.w, ra1.x, ra1.y, ra1.z, ra1.w};
            float rb[8] = {rb0.x, rb0.y, rb0.z, rb0.w, rb1.x, rb1.y, rb1.z, rb1.w};
#pragma unroll
            for (int i = 0; i < 8; i++)
#pragma unroll
                for (int j = 0; j < 8; j++) acc[i][j] += ra[i] * rb[j];
        }
    }
#pragma unroll
    for (int i = 0; i < 8; i++)
#pragma unroll
        for (int j = 0; j < 8; j++)
            epi(z, bm + ty * 8 + i, bn + tx * 8 + j, acc[i][j]);
}

// epilogues
struct EpiQKV {
    const float* bias;
    __device__ void operator()(int, int m, int n, float acc) const {
        float vv = acc + __ldg(bias + n);
        int which = n >> 10;
        int rem = n & 1023;
        int h = rem >> 6, d = rem & 63;
        int b = m >> 10, t = m & 1023;
        float* dst = which == 0 ? g_q : (which == 1 ? g_k : g_v);
        dst[((((long)b * CH + h) * CN + t) << 6) + d] = vv;
    }
};

struct EpiScores {
    __device__ void operator()(int z, int i, int j, float acc) const {
        int dd = i - j;
        dd = dd < -64 ? -64 : (dd > 64 ? 64 : dd);
        float vv = acc * CSCALE + g_qr[((long)z * CN + i) * CVOCAB + (dd + 64)];
        g_sc[((long)z * CN + i) * CN + j] = vv;
    }
};

// ---------------- split-bf16 attn@V (NN) with rel_v fused into order 0 -----
// block: 128 m-rows x full n=64; 8 warps (4m x 2n), warp tile 32m x 32n
// order 0 computes [attn | w] @ [V ; rel_v_emb(0..127)] + rank-1 (bucket 128)
__global__ void __launch_bounds__(256)
attnv_mma(const float* __restrict__ vin, float* __restrict__ vout,
          const float* __restrict__ alphas_raw, const float* __restrict__ relv,
          int order)
{
    __shared__ __nv_bfloat16 sAh[128][40], sAl[128][40];
    __shared__ __nv_bfloat16 sBh[64][40], sBl[64][40];
    const int z = blockIdx.y;
    const float* Amat = g_sc + (long)z * CN * CN;
    const float* Wmat = g_w + (long)z * CN * CWSTR;
    const float* Vin = vin + (long)z * CN * CDH;
    float* Vout = vout + (long)z * CN * CDH;
    float* Res = g_res + (long)z * CN * CDH;

    const int bm = blockIdx.x * 128;
    const int tid = threadIdx.x;
    const int w = tid >> 5, lane = tid & 31;
    const int wm = w & 3, wn = w >> 2;
    const int g = lane >> 2, t = lane & 3;
    const int lr = tid >> 1, lq = (tid & 1) * 16;
    const int vn = tid & 63, kp2 = (tid >> 6) * 2;

    float c[2][4][4];
#pragma unroll
    for (int mt = 0; mt < 2; mt++)
#pragma unroll
        for (int nt = 0; nt < 4; nt++)
#pragma unroll
            for (int e = 0; e < 4; e++) c[mt][nt][e] = 0.f;

    const int KTOT = (order == 0) ? CN + 128 : CN;

    for (int k0 = 0; k0 < KTOT; k0 += 32) {
        float4 a4[4];
        float vx0[4], vx1[4];
        if (k0 < CN) {
#pragma unroll
            for (int j = 0; j < 4; j++)
                a4[j] = *(const float4*)(Amat + (long)(bm + lr) * CN + k0 + lq + j * 4);
#pragma unroll
            for (int p = 0; p < 4; p++) {
                int kg = k0 + p * 8 + kp2;
                vx0[p] = Vin[(long)kg * CDH + vn];
                vx1[p] = Vin[(long)(kg + 1) * CDH + vn];
            }
        } else {
            int ke = k0 - CN;
#pragma unroll
            for (int j = 0; j < 4; j++)
                a4[j] = *(const float4*)(Wmat + (long)(bm + lr) * CWSTR + ke + lq + j * 4);
#pragma unroll
            for (int p = 0; p < 4; p++) {
                int kg = ke + p * 8 + kp2;
                vx0[p] = __ldg(relv + kg * CDH + vn);
                vx1[p] = __ldg(relv + (kg + 1) * CDH + vn);
            }
        }
        __syncthreads();
#pragma unroll
        for (int j = 0; j < 4; j++) {
            float xa[4] = {a4[j].x, a4[j].y, a4[j].z, a4[j].w};
#pragma unroll
            for (int e = 0; e < 4; e += 2) {
                __nv_bfloat16 h0, l0, h1, l1;
                split_bf16(xa[e], h0, l0); split_bf16(xa[e + 1], h1, l1);
                *(__nv_bfloat162*)&sAh[lr][lq + j * 4 + e] = __nv_bfloat162(h0, h1);
                *(__nv_bfloat162*)&sAl[lr][lq + j * 4 + e] = __nv_bfloat162(l0, l1);
            }
        }
#pragma unroll
        for (int p = 0; p < 4; p++) {
            __nv_bfloat16 h0, l0, h1, l1;
            split_bf16(vx0[p], h0, l0); split_bf16(vx1[p], h1, l1);
            *(__nv_bfloat162*)&sBh[vn][p * 8 + kp2] = __nv_bfloat162(h0, h1);
            *(__nv_bfloat162*)&sBl[vn][p * 8 + kp2] = __nv_bfloat162(l0, l1);
        }
        __syncthreads();
#pragma unroll
        for (int ks = 0; ks < 32; ks += 16) {
            unsigned Ah[2][4], Al[2][4], Bh[4][2], Bl[4][2];
#pragma unroll
            for (int mt = 0; mt < 2; mt++) {
                int r0 = wm * 32 + mt * 16 + g;
                Ah[mt][0] = *(const unsigned*)&sAh[r0][ks + 2 * t];
                Ah[mt][1] = *(const unsigned*)&sAh[r0 + 8][ks + 2 * t];
                Ah[mt][2] = *(const unsigned*)&sAh[r0][ks + 2 * t + 8];
                Ah[mt][3] = *(const unsigned*)&sAh[r0 + 8][ks + 2 * t + 8];
                Al[mt][0] = *(const unsigned*)&sAl[r0][ks + 2 * t];
                Al[mt][1] = *(const unsigned*)&sAl[r0 + 8][ks + 2 * t];
                Al[mt][2] = *(const unsigned*)&sAl[r0][ks + 2 * t + 8];
                Al[mt][3] = *(const unsigned*)&sAl[r0 + 8][ks + 2 * t + 8];
            }
#pragma unroll
            for (int nt = 0; nt < 4; nt++) {
                int n0 = wn * 32 + nt * 8 + g;
                Bh[nt][0] = *(const unsigned*)&sBh[n0][ks + 2 * t];
                Bh[nt][1] = *(const unsigned*)&sBh[n0][ks + 2 * t + 8];
                Bl[nt][0] = *(const unsigned*)&sBl[n0][ks + 2 * t];
                Bl[nt][1] = *(const unsigned*)&sBl[n0][ks + 2 * t + 8];
            }
#pragma unroll
            for (int mt = 0; mt < 2; mt++)
#pragma unroll
                for (int nt = 0; nt < 4; nt++) {
                    MMA16816(c[mt][nt], Ah[mt], Bh[nt]);
                    MMA16816(c[mt][nt], Al[mt], Bh[nt]);
                    MMA16816(c[mt][nt], Ah[mt], Bl[nt]);
                }
        }
    }

    const int h = z & 15;
    const float alpha = 1.f / (1.f + __expf(-__ldg(alphas_raw + order * CH + h)));
#pragma unroll
    for (int mt = 0; mt < 2; mt++)
#pragma unroll
        for (int nt = 0; nt < 4; nt++)
#pragma unroll
            for (int e = 0; e < 4; e++) {
                int row = bm + wm * 32 + mt * 16 + g + (e >= 2 ? 8 : 0);
                int col = wn * 32 + nt * 8 + 2 * t + (e & 1);
                long idx = (long)row * CDH + col;
                float val = c[mt][nt][e];
                if (order == 0) {
                    // bucket-128 rank-1 term, exact fp32
                    val += __ldg(&Wmat[(long)row * CWSTR + 128]) *
                           __ldg(relv + 128 * CDH + col);
                    Vout[idx] = val;
                    Res[idx] = alpha * val;
                } else {
                    Vout[idx] = val;
                    Res[idx] += alpha * val;
                }
            }
}

// ---------------- out-projection, split-bf16, transpose fused into A-load --
// out[m, n] = sum_k res[b, h, t, d] * Wout[n, k] + bout[n],  m=b*1024+t, k=h*64+d
__global__ void __launch_bounds__(256)
outproj_mma(const float* __restrict__ Wout, const float* __restrict__ bout,
            float* __restrict__ out)
{
    __shared__ __nv_bfloat16 sAh[128][40], sAl[128][40];
    __shared__ __nv_bfloat16 sBh[128][40], sBl[128][40];
    const int bm = blockIdx.y * 128;
    const int bn = blockIdx.x * 128;
    const int tid = threadIdx.x;
    const int w = tid >> 5, lane = tid & 31;
    const int wm = w & 3, wn = w >> 2;
    const int g = lane >> 2, t = lane & 3;
    const int lr = tid >> 1, lq = (tid & 1) * 16;

    float c[2][8][4];
#pragma unroll
    for (int mt = 0; mt < 2; mt++)
#pragma unroll
        for (int nt = 0; nt < 8; nt++)
#pragma unroll
            for (int e = 0; e < 4; e++) c[mt][nt][e] = 0.f;

    // A addressing: m = bm+lr -> (b, n); k = h*64+d
    const int m = bm + lr;
    const int bb = m >> 10, nn = m & 1023;
    const float* Abase = g_res + (((long)bb * CH * CN + nn) << 6);
    const float* Bp = Wout + (long)(bn + lr) * CDIM + lq;

    for (int k0 = 0; k0 < CDIM; k0 += 32) {
        int kl = k0 + lq;
        int hh = kl >> 6, d0 = kl & 63;
        const float* Ap = Abase + ((long)hh * CN << 6) + d0;
        float4 a4[4], b4[4];
#pragma unroll
        for (int j = 0; j < 4; j++) {
            a4[j] = *(const float4*)(Ap + j * 4);
            b4[j] = *(const float4*)(Bp + k0 + j * 4);
        }
        __syncthreads();
#pragma unroll
        for (int j = 0; j < 4; j++) {
            float xa[4] = {a4[j].x, a4[j].y, a4[j].z, a4[j].w};
            float xb[4] = {b4[j].x, b4[j].y, b4[j].z, b4[j].w};
#pragma unroll
            for (int e = 0; e < 4; e += 2) {
                __nv_bfloat16 h0, l0, h1, l1;
                split_bf16(xa[e], h0, l0); split_bf16(xa[e + 1], h1, l1);
                *(__nv_bfloat162*)&sAh[lr][lq + j * 4 + e] = __nv_bfloat162(h0, h1);
                *(__nv_bfloat162*)&sAl[lr][lq + j * 4 + e] = __nv_bfloat162(l0, l1);
                split_bf16(xb[e], h0, l0); split_bf16(xb[e + 1], h1, l1);
                *(__nv_bfloat162*)&sBh[lr][lq + j * 4 + e] = __nv_bfloat162(h0, h1);
                *(__nv_bfloat162*)&sBl[lr][lq + j * 4 + e] = __nv_bfloat162(l0, l1);
            }
        }
        __syncthreads();
#pragma unroll
        for (int ks = 0; ks < 32; ks += 16) {
            unsigned Ah[2][4], Al[2][4], Bh[8][2], Bl[8][2];
#pragma unroll
            for (int mt = 0; mt < 2; mt++) {
                int r0 = wm * 32 + mt * 16 + g;
                Ah[mt][0] = *(const unsigned*)&sAh[r0][ks + 2 * t];
                Ah[mt][1] = *(const unsigned*)&sAh[r0 + 8][ks + 2 * t];
                Ah[mt][2] = *(const unsigned*)&sAh[r0][ks + 2 * t + 8];
                Ah[mt][3] = *(const unsigned*)&sAh[r0 + 8][ks + 2 * t + 8];
                Al[mt][0] = *(const unsigned*)&sAl[r0][ks + 2 * t];
                Al[mt][1] = *(const unsigned*)&sAl[r0 + 8][ks + 2 * t];
                Al[mt][2] = *(const unsigned*)&sAl[r0][ks + 2 * t + 8];
                Al[mt][3] = *(const unsigned*)&sAl[r0 + 8][ks + 2 * t + 8];
            }
#pragma unroll
            for (int nt = 0; nt < 8; nt++) {
                int n0 = wn * 64 + nt * 8 + g;
                Bh[nt][0] = *(const unsigned*)&sBh[n0][ks + 2 * t];
                Bh[nt][1] = *(const unsigned*)&sBh[n0][ks + 2 * t + 8];
                Bl[nt][0] = *(const unsigned*)&sBl[n0][ks + 2 * t];
                Bl[nt][1] = *(const unsigned*)&sBl[n0][ks + 2 * t + 8];
            }
#pragma unroll
            for (int mt = 0; mt < 2; mt++)
#pragma unroll
                for (int nt = 0; nt < 8; nt++) {
                    MMA16816(c[mt][nt], Ah[mt], Bh[nt]);
                    MMA16816(c[mt][nt], Al[mt], Bh[nt]);
                    MMA16816(c[mt][nt], Ah[mt], Bl[nt]);
                }
        }
    }
#pragma unroll
    for (int mt = 0; mt < 2; mt++)
#pragma unroll
        for (int nt = 0; nt < 8; nt++) {
            int row = bm + wm * 32 + mt * 16 + g;
            int col = bn + wn * 64 + nt * 8 + 2 * t;
            out[(long)row * CDIM + col] = c[mt][nt][0] + __ldg(bout + col);
            out[(long)row * CDIM + col + 1] = c[mt][nt][1] + __ldg(bout + col + 1);
            out[(long)(row + 8) * CDIM + col] = c[mt][nt][2] + __ldg(bout + col);
            out[(long)(row + 8) * CDIM + col + 1] = c[mt][nt][3] + __ldg(bout + col + 1);
        }
}

// ---------------- qr[row, v] = dot(q[row,:], rel_k_emb[v,:]) ---------------
__global__ void __launch_bounds__(256)
qr_kernel(const float* __restrict__ relk)
{
    __shared__ float sembT[CDH][132]; // transposed [d][v], padded
    __shared__ float sq[32][CDH];
    const int row0 = blockIdx.x * 32;
    for (int idx = threadIdx.x; idx < CVOCAB * CDH; idx += 256) {
        int v = idx >> 6, d = idx & 63;
        sembT[d][v] = relk[idx];
    }
    for (int d = threadIdx.x; d < CDH; d += 256) {
        sembT[d][129] = 0.f; sembT[d][130] = 0.f; sembT[d][131] = 0.f;
    }
    for (int idx = threadIdx.x; idx < 32 * CDH; idx += 256)
        sq[idx >> 6][idx & 63] = g_q[(long)row0 * CDH + idx];
    __syncthreads();

    for (int t = threadIdx.x; t < 32 * 33; t += 256) {
        int r = t / 33, vg = t % 33;
        float4 acc = make_float4(0.f, 0.f, 0.f, 0.f);
#pragma unroll 16
        for (int d = 0; d < CDH; d++) {
            float qd = sq[r][d];
            float4 e = *(const float4*)&sembT[d][vg * 4];
            acc.x += qd * e.x; acc.y += qd * e.y;
            acc.z += qd * e.z; acc.w += qd * e.w;
        }
        int v0 = vg * 4;
        long base = (long)(row0 + r) * CVOCAB + v0;
        g_qr[base + 0] = acc.x;
        if (v0 + 1 < CVOCAB) g_qr[base + 1] = acc.y;
        if (v0 + 2 < CVOCAB) g_qr[base + 2] = acc.z;
        if (v0 + 3 < CVOCAB) g_qr[base + 3] = acc.w;
    }
}

// ---------------- top-k threshold + masked softmax + rel_v weights ---------
__device__ __forceinline__ unsigned fkey(float f)
{
    unsigned u = __float_as_uint(f);
    return (u & 0x80000000u) ? ~u : (u | 0x80000000u);
}
__device__ __forceinline__ float fkeyinv(unsigned u)
{
    return __uint_as_float((u & 0x80000000u) ? (u & 0x7FFFFFFFu) : ~u);
}

__global__ void __launch_bounds__(256)
topk_softmax_w_kernel()
{
    const long row = blockIdx.x;
    const int i = (int)(row & 1023);
    float* S = g_sc + row * CN;
    __shared__ unsigned hist[256];
    __shared__ float red[16];
    __shared__ float w[132];
    __shared__ unsigned s_prefix, s_k;
    __shared__ float s_max, s_sum;
    const int tid = threadIdx.x;
    const int lane = tid & 31, wid = tid >> 5;

    float4 v4 = ((const float4*)S)[tid];
    float v[4] = {v4.x, v4.y, v4.z, v4.w};
    unsigned u[4];
#pragma unroll
    for (int j = 0; j < 4; j++) u[j] = fkey(v[j]);
    if (tid == 0) { s_prefix = 0u; s_k = CTOPK; }
    if (tid < 132) w[tid] = 0.f;

#pragma unroll
    for (int pass = 0; pass < 4; pass++) {
        const int shift = 24 - pass * 8;
        hist[tid] = 0u;
        __syncthreads();
        const unsigned prefix = s_prefix;
#pragma unroll
        for (int j = 0; j < 4; j++) {
            bool ok = (pass == 0) || (((u[j] ^ prefix) >> (shift + 8)) == 0u);
            unsigned bin = (u[j] >> shift) & 255u;
            unsigned key = ok ? bin : 0xFFFFFFFFu;
            unsigned mm = __match_any_sync(0xFFFFFFFFu, key);
            if (ok && lane == (unsigned)(__ffs(mm) - 1))
                atomicAdd(&hist[bin], (unsigned)__popc(mm));
        }
        __syncthreads();
        if (tid < 32) {
            unsigned h8[8]; unsigned t = 0;
#pragma unroll
            for (int j = 0; j < 8; j++) { h8[j] = hist[tid * 8 + j]; t += h8[j]; }
            unsigned s = t;
#pragma unroll
            for (int off = 1; off < 32; off <<= 1) {
                unsigned vv = __shfl_down_sync(0xFFFFFFFFu, s, off);
                if (tid + off < 32) s += vv;
            }
            unsigned prev = s - t;             // suffix count above this 8-bin group
            const unsigned pref = s_prefix;
            const unsigned kcur = s_k;
#pragma unroll
            for (int j = 7; j >= 0; j--) {
                unsigned cur = prev + h8[j];
                if (cur >= kcur && prev < kcur) {
                    s_prefix = pref | ((unsigned)(tid * 8 + j) << shift);
                    s_k = kcur - prev;
                }
                prev = cur;
            }
        }
        __syncthreads();
    }
    const float thr = fkeyinv(s_prefix);

    // row max (top element is always kept)
    float lm = fmaxf(fmaxf(v[0], v[1]), fmaxf(v[2], v[3]));
#pragma unroll
    for (int off = 16; off > 0; off >>= 1)
        lm = fmaxf(lm, __shfl_xor_sync(0xFFFFFFFFu, lm, off));
    if (lane == 0) red[wid] = lm;
    __syncthreads();
    if (tid == 0) {
        float m0 = red[0];
#pragma unroll
        for (int q = 1; q < 8; q++) m0 = fmaxf(m0, red[q]);
        s_max = m0;
    }
    __syncthreads();
    const float mx = s_max;

    float a[4];
    float ls = 0.f;
#pragma unroll
    for (int j = 0; j < 4; j++) {
        a[j] = (v[j] < thr) ? 0.f : __expf(v[j] - mx);
        ls += a[j];
    }
#pragma unroll
    for (int off = 16; off > 0; off >>= 1)
        ls += __shfl_xor_sync(0xFFFFFFFFu, ls, off);
    if (lane == 0) red[wid] = ls;
    __syncthreads();
    if (tid == 0) {
        float s0 = 0.f;
#pragma unroll
        for (int q = 0; q < 8; q++) s0 += red[q];
        s_sum = s0;
    }
    __syncthreads();
    const float inv = 1.f / s_sum;
#pragma unroll
    for (int j = 0; j < 4; j++) a[j] *= inv;
    ((float4*)S)[tid] = make_float4(a[0], a[1], a[2], a[3]);

    // rel_v bucket weights: bucket(e) = clip(i-e, -64, 64) + 64
    float l0 = 0.f, l1 = 0.f;
#pragma unroll
    for (int j = 0; j < 4; j++) {
        int e = tid * 4 + j;
        int del = i - e;
        if (del <= -64) l0 += a[j];
        else if (del >= 64) l1 += a[j];
        else w[del + 64] = a[j];   // unique writer per bucket
    }
#pragma unroll
    for (int off = 16; off > 0; off >>= 1) {
        l0 += __shfl_xor_sync(0xFFFFFFFFu, l0, off);
        l1 += __shfl_xor_sync(0xFFFFFFFFu, l1, off);
    }
    if (lane == 0) { red[wid] = l0; red[8 + wid] = l1; }
    __syncthreads();
    if (tid == 0) {
        float s0 = 0.f, s1 = 0.f;
#pragma unroll
        for (int q = 0; q < 8; q++) { s0 += red[q]; s1 += red[8 + q]; }
        w[0] = s0; w[128] = s1;
    }
    __syncthreads();

    if (tid < CVOCAB) g_w[row * CWSTR + tid] = w[tid];
}

// ---------------- host launcher --------------------------------------------
extern "C" void kernel_launch(void* const* d_in, const int* in_sizes, int n_in,
                              void* d_out, int out_size)
{
    (void)in_sizes; (void)n_in; (void)out_size;
    const float* x      = (const float*)d_in[0];
    const float* Wqkv   = (const float*)d_in[1];
    const float* bqkv   = (const float*)d_in[2];
    const float* Wout   = (const float*)d_in[3];
    const float* bout   = (const float*)d_in[4];
    const float* relk   = (const float*)d_in[5];
    const float* relv   = (const float*)d_in[6];
    const float* alphas = (const float*)d_in[7];
    float* out = (float*)d_out;

    float *p_q, *p_k, *p_v, *p_t0, *p_t1;
    cudaGetSymbolAddress((void**)&p_q, g_q);
    cudaGetSymbolAddress((void**)&p_k, g_k);
    cudaGetSymbolAddress((void**)&p_v, g_v);
    cudaGetSymbolAddress((void**)&p_t0, g_t0);
    cudaGetSymbolAddress((void**)&p_t1, g_t1);

    // 1) QKV projection (fp32 exact: feeds the top-k threshold)
    sgemm_nt<<<dim3(3072 / 128, 4096 / 128, 1), 256>>>(
        x, Wqkv, 0L, 0L, 4096, 3072, 1024, EpiQKV{bqkv});

    // 2) q . rel_k_emb table
    qr_kernel<<<CROWS / 32, 256>>>(relk);

    // 3) scores = scale * q@k^T + qr gather (fp32 exact, batched over 64 bh)
    sgemm_nt<<<dim3(CN / 128, CN / 128, CBH), 256>>>(
        p_q, p_k, (long)CN * CDH, (long)CN * CDH, CN, CN, CDH, EpiScores{});

    // 4) exact top-256 threshold + masked softmax + rel_v bucket weights
    topk_softmax_w_kernel<<<CROWS, 256>>>();

    // 5-7) attn @ V chain on tensor cores; rel_v fused into order 0
    attnv_mma<<<dim3(CN / 128, CBH), 256>>>(p_v, p_t0, alphas, relv, 0);
    attnv_mma<<<dim3(CN / 128, CBH), 256>>>(p_t0, p_t1, alphas, relv, 1);
    attnv_mma<<<dim3(CN / 128, CBH), 256>>>(p_t1, p_t0, alphas, relv, 2);

    // 8) output projection on tensor cores, head-transpose fused into A-load
    outproj_mma<<<dim3(CDIM / 128, 4096 / 128, 1), 256>>>(Wout, bout, out);
}

// round 14
// speedup vs baseline: 1.3020x; 1.0115x over previous
#include <cuda_runtime.h>
#include <cuda_bf16.h>
#include <math.h>

#define CB 4
#define CN 1024
#define CDIM 1024
#define CH 16
#define CDH 64
#define CINNER 1024
#define CVOCAB 129
#define CBH 64
#define CTOPK 256
#define CSCALE 0.125f
#define CROWS (CBH * CN) /* 65536 */
#define CWSTR 132        /* g_w row stride */

// ---------------- scratch (device globals; no allocation allowed) ----------
__device__ __align__(128) float g_q[CBH * CN * CDH];
__device__ __align__(128) float g_k[CBH * CN * CDH];
__device__ __align__(128) float g_v[CBH * CN * CDH];
__device__ __align__(128) float g_qr[(size_t)CROWS * CVOCAB];
__device__ __align__(128) float g_sc[(size_t)CBH * CN * CN]; // scores -> attn (256MB)
__device__ __align__(128) float g_w[(size_t)CROWS * CWSTR];  // rel_v bucket weights
__device__ __align__(128) float g_t0[CBH * CN * CDH];
__device__ __align__(128) float g_t1[CBH * CN * CDH];
__device__ __align__(128) float g_res[CBH * CN * CDH];

// ---------------- bf16 split helpers ---------------------------------------
__device__ __forceinline__ void split_bf16(float x, __nv_bfloat16& h, __nv_bfloat16& l)
{
    h = __float2bfloat16(x);
    l = __float2bfloat16(x - __bfloat162float(h));
}

#define MMA16816(c, a, b)                                                     \
    asm volatile(                                                             \
        "mma.sync.aligned.m16n8k16.row.col.f32.bf16.bf16.f32 "                \
        "{%0,%1,%2,%3},{%4,%5,%6,%7},{%8,%9},{%0,%1,%2,%3};"                  \
        : "+f"((c)[0]), "+f"((c)[1]), "+f"((c)[2]), "+f"((c)[3])              \
        : "r"((a)[0]), "r"((a)[1]), "r"((a)[2]), "r"((a)[3]),                 \
          "r"((b)[0]), "r"((b)[1]))

// ---------------- generic 128x128x8 NT SGEMM (fp32 exact) ------------------
template <class Epi>
__global__ void __launch_bounds__(256)
sgemm_nt(const float* __restrict__ A, const float* __restrict__ Bm,
         long sA, long sB, int M, int Nn, int K, Epi epi)
{
    __shared__ float As[8][128];
    __shared__ float Bs[8][128];
    const int z = blockIdx.z;
    A += (long)z * sA;
    Bm += (long)z * sB;
    const int bm = blockIdx.y * 128;
    const int bn = blockIdx.x * 128;
    const int tid = threadIdx.x;
    const int ty = tid >> 4;
    const int tx = tid & 15;
    const int lr = tid >> 1;
    const int lc = (tid & 1) * 4;
    float acc[8][8];
#pragma unroll
    for (int i = 0; i < 8; i++)
#pragma unroll
        for (int j = 0; j < 8; j++) acc[i][j] = 0.f;

    const float* Ap = A + (long)(bm + lr) * K + lc;
    const float* Bp = Bm + (long)(bn + lr) * K + lc;

    for (int k0 = 0; k0 < K; k0 += 8) {
        float4 a4 = *(const float4*)(Ap + k0);
        float4 b4 = *(const float4*)(Bp + k0);
        __syncthreads();
        As[lc + 0][lr] = a4.x; As[lc + 1][lr] = a4.y;
        As[lc + 2][lr] = a4.z; As[lc + 3][lr] = a4.w;
        Bs[lc + 0][lr] = b4.x; Bs[lc + 1][lr] = b4.y;
        Bs[lc + 2][lr] = b4.z; Bs[lc + 3][lr] = b4.w;
        __syncthreads();
#pragma unroll
        for (int kk = 0; kk < 8; kk++) {
            float4 ra0 = *(const float4*)&As[kk][ty * 8];
            float4 ra1 = *(const float4*)&As[kk][ty * 8 + 4];
            float4 rb0 = *(const float4*)&Bs[kk][tx * 8];
            float4 rb1 = *(const float4*)&Bs[kk][tx * 8 + 4];
            float ra[8] = {ra0.x, ra0.y, ra0.z, ra0.w, ra1.x, ra1.y, ra1.z, ra1.w};
            float rb[8] = {rb0.x, rb0.y, rb0.z, rb0.w, rb1.x, rb1.y, rb1.z, rb1.w};
#pragma unroll
            for (int i = 0; i < 8; i++)
#pragma unroll
                for (int j = 0; j < 8; j++) acc[i][j] += ra[i] * rb[j];
        }
    }
#pragma unroll
    for (int i = 0; i < 8; i++)
#pragma unroll
        for (int j = 0; j < 8; j++)
            epi(z, bm + ty * 8 + i, bn + tx * 8 + j, acc[i][j]);
}

// epilogues
struct EpiQK {
    const float* bias;
    __device__ void operator()(int, int m, int n, float acc) const {
        float vv = acc + __ldg(bias + n);
        int which = n >> 10;          // 0 = q, 1 = k
        int rem = n & 1023;
        int h = rem >> 6, d = rem & 63;
        int b = m >> 10, t = m & 1023;
        float* dst = which == 0 ? g_q : g_k;
        dst[((((long)b * CH + h) * CN + t) << 6) + d] = vv;
    }
};

struct EpiV {
    const float* bias;               // points at bqkv + 2048
    __device__ void operator()(int, int m, int n, float acc) const {
        float vv = acc + __ldg(bias + n);
        int h = n >> 6, d = n & 63;
        int b = m >> 10, t = m & 1023;
        g_v[((((long)b * CH + h) * CN + t) << 6) + d] = vv;
    }
};

struct EpiScores {
    __device__ void operator()(int z, int i, int j, float acc) const {
        int dd = i - j;
        dd = dd < -64 ? -64 : (dd > 64 ? 64 : dd);
        float vv = acc * CSCALE + g_qr[((long)z * CN + i) * CVOCAB + (dd + 64)];
        g_sc[((long)z * CN + i) * CN + j] = vv;
    }
};

// ---------------- split-bf16 tensor-core NT GEMM (V projection) ------------
// block 128x128, 8 warps (4m x 2n), warp tile 32x64, k-chunk 32
template <class Epi>
__global__ void __launch_bounds__(256)
bgemm_nt_mma(const float* __restrict__ A, const float* __restrict__ Bm,
             int M, int Nn, int K, Epi epi)
{
    __shared__ __nv_bfloat16 sAh[128][40], sAl[128][40];
    __shared__ __nv_bfloat16 sBh[128][40], sBl[128][40];
    const int bm = blockIdx.y * 128;
    const int bn = blockIdx.x * 128;
    const int tid = threadIdx.x;
    const int w = tid >> 5, lane = tid & 31;
    const int wm = w & 3, wn = w >> 2;
    const int g = lane >> 2, t = lane & 3;
    const int lr = tid >> 1, lq = (tid & 1) * 16;

    float c[2][8][4];
#pragma unroll
    for (int mt = 0; mt < 2; mt++)
#pragma unroll
        for (int nt = 0; nt < 8; nt++)
#pragma unroll
            for (int e = 0; e < 4; e++) c[mt][nt][e] = 0.f;

    const float* Ap = A + (long)(bm + lr) * K + lq;
    const float* Bp = Bm + (long)(bn + lr) * K + lq;

    for (int k0 = 0; k0 < K; k0 += 32) {
        float4 a4[4], b4[4];
#pragma unroll
        for (int j = 0; j < 4; j++) {
            a4[j] = *(const float4*)(Ap + k0 + j * 4);
            b4[j] = *(const float4*)(Bp + k0 + j * 4);
        }
        __syncthreads();
#pragma unroll
        for (int j = 0; j < 4; j++) {
            float xa[4] = {a4[j].x, a4[j].y, a4[j].z, a4[j].w};
            float xb[4] = {b4[j].x, b4[j].y, b4[j].z, b4[j].w};
#pragma unroll
            for (int e = 0; e < 4; e += 2) {
                __nv_bfloat16 h0, l0, h1, l1;
                split_bf16(xa[e], h0, l0); split_bf16(xa[e + 1], h1, l1);
                *(__nv_bfloat162*)&sAh[lr][lq + j * 4 + e] = __nv_bfloat162(h0, h1);
                *(__nv_bfloat162*)&sAl[lr][lq + j * 4 + e] = __nv_bfloat162(l0, l1);
                split_bf16(xb[e], h0, l0); split_bf16(xb[e + 1], h1, l1);
                *(__nv_bfloat162*)&sBh[lr][lq + j * 4 + e] = __nv_bfloat162(h0, h1);
                *(__nv_bfloat162*)&sBl[lr][lq + j * 4 + e] = __nv_bfloat162(l0, l1);
            }
        }
        __syncthreads();
#pragma unroll
        for (int ks = 0; ks < 32; ks += 16) {
            unsigned Ah[2][4], Al[2][4], Bh[8][2], Bl[8][2];
#pragma unroll
            for (int mt = 0; mt < 2; mt++) {
                int r0 = wm * 32 + mt * 16 + g;
                Ah[mt][0] = *(const unsigned*)&sAh[r0][ks + 2 * t];
                Ah[mt][1] = *(const unsigned*)&sAh[r0 + 8][ks + 2 * t];
                Ah[mt][2] = *(const unsigned*)&sAh[r0][ks + 2 * t + 8];
                Ah[mt][3] = *(const unsigned*)&sAh[r0 + 8][ks + 2 * t + 8];
                Al[mt][0] = *(const unsigned*)&sAl[r0][ks + 2 * t];
                Al[mt][1] = *(const unsigned*)&sAl[r0 + 8][ks + 2 * t];
                Al[mt][2] = *(const unsigned*)&sAl[r0][ks + 2 * t + 8];
                Al[mt][3] = *(const unsigned*)&sAl[r0 + 8][ks + 2 * t + 8];
            }
#pragma unroll
            for (int nt = 0; nt < 8; nt++) {
                int n0 = wn * 64 + nt * 8 + g;
                Bh[nt][0] = *(const unsigned*)&sBh[n0][ks + 2 * t];
                Bh[nt][1] = *(const unsigned*)&sBh[n0][ks + 2 * t + 8];
                Bl[nt][0] = *(const unsigned*)&sBl[n0][ks + 2 * t];
                Bl[nt][1] = *(const unsigned*)&sBl[n0][ks + 2 * t + 8];
            }
#pragma unroll
            for (int mt = 0; mt < 2; mt++)
#pragma unroll
                for (int nt = 0; nt < 8; nt++) {
                    MMA16816(c[mt][nt], Ah[mt], Bh[nt]);
                    MMA16816(c[mt][nt], Al[mt], Bh[nt]);
                    MMA16816(c[mt][nt], Ah[mt], Bl[nt]);
                }
        }
    }
#pragma unroll
    for (int mt = 0; mt < 2; mt++)
#pragma unroll
        for (int nt = 0; nt < 8; nt++) {
            int row = bm + wm * 32 + mt * 16 + g;
            int col = bn + wn * 64 + nt * 8 + 2 * t;
            epi(0, row, col, c[mt][nt][0]);
            epi(0, row, col + 1, c[mt][nt][1]);
            epi(0, row + 8, col, c[mt][nt][2]);
            epi(0, row + 8, col + 1, c[mt][nt][3]);
        }
}

// ---------------- split-bf16 attn@V (NN) with rel_v fused into order 0 -----
__global__ void __launch_bounds__(256)
attnv_mma(const float* __restrict__ vin, float* __restrict__ vout,
          const float* __restrict__ alphas_raw, const float* __restrict__ relv,
          int order)
{
    __shared__ __nv_bfloat16 sAh[128][40], sAl[128][40];
    __shared__ __nv_bfloat16 sBh[64][40], sBl[64][40];
    const int z = blockIdx.y;
    const float* Amat = g_sc + (long)z * CN * CN;
    const float* Wmat = g_w + (long)z * CN * CWSTR;
    const float* Vin = vin + (long)z * CN * CDH;
    float* Vout = vout + (long)z * CN * CDH;
    float* Res = g_res + (long)z * CN * CDH;

    const int bm = blockIdx.x * 128;
    const int tid = threadIdx.x;
    const int w = tid >> 5, lane = tid & 31;
    const int wm = w & 3, wn = w >> 2;
    const int g = lane >> 2, t = lane & 3;
    const int lr = tid >> 1, lq = (tid & 1) * 16;
    const int vn = tid & 63, kp2 = (tid >> 6) * 2;

    float c[2][4][4];
#pragma unroll
    for (int mt = 0; mt < 2; mt++)
#pragma unroll
        for (int nt = 0; nt < 4; nt++)
#pragma unroll
            for (int e = 0; e < 4; e++) c[mt][nt][e] = 0.f;

    const int KTOT = (order == 0) ? CN + 128 : CN;

    for (int k0 = 0; k0 < KTOT; k0 += 32) {
        float4 a4[4];
        float vx0[4], vx1[4];
        if (k0 < CN) {
#pragma unroll
            for (int j = 0; j < 4; j++)
                a4[j] = *(const float4*)(Amat + (long)(bm + lr) * CN + k0 + lq + j * 4);
#pragma unroll
            for (int p = 0; p < 4; p++) {
                int kg = k0 + p * 8 + kp2;
                vx0[p] = Vin[(long)kg * CDH + vn];
                vx1[p] = Vin[(long)(kg + 1) * CDH + vn];
            }
        } else {
            int ke = k0 - CN;
#pragma unroll
            for (int j = 0; j < 4; j++)
                a4[j] = *(const float4*)(Wmat + (long)(bm + lr) * CWSTR + ke + lq + j * 4);
#pragma unroll
            for (int p = 0; p < 4; p++) {
                int kg = ke + p * 8 + kp2;
                vx0[p] = __ldg(relv + kg * CDH + vn);
                vx1[p] = __ldg(relv + (kg + 1) * CDH + vn);
            }
        }
        __syncthreads();
#pragma unroll
        for (int j = 0; j < 4; j++) {
            float xa[4] = {a4[j].x, a4[j].y, a4[j].z, a4[j].w};
#pragma unroll
            for (int e = 0; e < 4; e += 2) {
                __nv_bfloat16 h0, l0, h1, l1;
                split_bf16(xa[e], h0, l0); split_bf16(xa[e + 1], h1, l1);
                *(__nv_bfloat162*)&sAh[lr][lq + j * 4 + e] = __nv_bfloat162(h0, h1);
                *(__nv_bfloat162*)&sAl[lr][lq + j * 4 + e] = __nv_bfloat162(l0, l1);
            }
        }
#pragma unroll
        for (int p = 0; p < 4; p++) {
            __nv_bfloat16 h0, l0, h1, l1;
            split_bf16(vx0[p], h0, l0); split_bf16(vx1[p], h1, l1);
            *(__nv_bfloat162*)&sBh[vn][p * 8 + kp2] = __nv_bfloat162(h0, h1);
            *(__nv_bfloat162*)&sBl[vn][p * 8 + kp2] = __nv_bfloat162(l0, l1);
        }
        __syncthreads();
#pragma unroll
        for (int ks = 0; ks < 32; ks += 16) {
            unsigned Ah[2][4], Al[2][4], Bh[4][2], Bl[4][2];
#pragma unroll
            for (int mt = 0; mt < 2; mt++) {
                int r0 = wm * 32 + mt * 16 + g;
                Ah[mt][0] = *(const unsigned*)&sAh[r0][ks + 2 * t];
                Ah[mt][1] = *(const unsigned*)&sAh[r0 + 8][ks + 2 * t];
                Ah[mt][2] = *(const unsigned*)&sAh[r0][ks + 2 * t + 8];
                Ah[mt][3] = *(const unsigned*)&sAh[r0 + 8][ks + 2 * t + 8];
                Al[mt][0] = *(const unsigned*)&sAl[r0][ks + 2 * t];
                Al[mt][1] = *(const unsigned*)&sAl[r0 + 8][ks + 2 * t];
                Al[mt][2] = *(const unsigned*)&sAl[r0][ks + 2 * t + 8];
                Al[mt][3] = *(const unsigned*)&sAl[r0 + 8][ks + 2 * t + 8];
            }
#pragma unroll
            for (int nt = 0; nt < 4; nt++) {
                int n0 = wn * 32 + nt * 8 + g;
                Bh[nt][0] = *(const unsigned*)&sBh[n0][ks + 2 * t];
                Bh[nt][1] = *(const unsigned*)&sBh[n0][ks + 2 * t + 8];
                Bl[nt][0] = *(const unsigned*)&sBl[n0][ks + 2 * t];
                Bl[nt][1] = *(const unsigned*)&sBl[n0][ks + 2 * t + 8];
            }
#pragma unroll
            for (int mt = 0; mt < 2; mt++)
#pragma unroll
                for (int nt = 0; nt < 4; nt++) {
                    MMA16816(c[mt][nt], Ah[mt], Bh[nt]);
                    MMA16816(c[mt][nt], Al[mt], Bh[nt]);
                    MMA16816(c[mt][nt], Ah[mt], Bl[nt]);
                }
        }
    }

    const int h = z & 15;
    const float alpha = 1.f / (1.f + __expf(-__ldg(alphas_raw + order * CH + h)));
#pragma unroll
    for (int mt = 0; mt < 2; mt++)
#pragma unroll
        for (int nt = 0; nt < 4; nt++)
#pragma unroll
            for (int e = 0; e < 4; e++) {
                int row = bm + wm * 32 + mt * 16 + g + (e >= 2 ? 8 : 0);
                int col = wn * 32 + nt * 8 + 2 * t + (e & 1);
                long idx = (long)row * CDH + col;
                float val = c[mt][nt][e];
                if (order == 0) {
                    val += __ldg(&Wmat[(long)row * CWSTR + 128]) *
                           __ldg(relv + 128 * CDH + col);
                    Vout[idx] = val;
                    Res[idx] = alpha * val;
                } else {
                    Vout[idx] = val;
                    Res[idx] += alpha * val;
                }
            }
}

// ---------------- out-projection, split-bf16, transpose fused into A-load --
__global__ void __launch_bounds__(256)
outproj_mma(const float* __restrict__ Wout, const float* __restrict__ bout,
            float* __restrict__ out)
{
    __shared__ __nv_bfloat16 sAh[128][40], sAl[128][40];
    __shared__ __nv_bfloat16 sBh[128][40], sBl[128][40];
    const int bm = blockIdx.y * 128;
    const int bn = blockIdx.x * 128;
    const int tid = threadIdx.x;
    const int w = tid >> 5, lane = tid & 31;
    const int wm = w & 3, wn = w >> 2;
    const int g = lane >> 2, t = lane & 3;
    const int lr = tid >> 1, lq = (tid & 1) * 16;

    float c[2][8][4];
#pragma unroll
    for (int mt = 0; mt < 2; mt++)
#pragma unroll
        for (int nt = 0; nt < 8; nt++)
#pragma unroll
            for (int e = 0; e < 4; e++) c[mt][nt][e] = 0.f;

    const int m = bm + lr;
    const int bb = m >> 10, nn = m & 1023;
    const float* Abase = g_res + (((long)bb * CH * CN + nn) << 6);
    const float* Bp = Wout + (long)(bn + lr) * CDIM + lq;

    for (int k0 = 0; k0 < CDIM; k0 += 32) {
        int kl = k0 + lq;
        int hh = kl >> 6, d0 = kl & 63;
        const float* Ap = Abase + ((long)hh * CN << 6) + d0;
        float4 a4[4], b4[4];
#pragma unroll
        for (int j = 0; j < 4; j++) {
            a4[j] = *(const float4*)(Ap + j * 4);
            b4[j] = *(const float4*)(Bp + k0 + j * 4);
        }
        __syncthreads();
#pragma unroll
        for (int j = 0; j < 4; j++) {
            float xa[4] = {a4[j].x, a4[j].y, a4[j].z, a4[j].w};
            float xb[4] = {b4[j].x, b4[j].y, b4[j].z, b4[j].w};
#pragma unroll
            for (int e = 0; e < 4; e += 2) {
                __nv_bfloat16 h0, l0, h1, l1;
                split_bf16(xa[e], h0, l0); split_bf16(xa[e + 1], h1, l1);
                *(__nv_bfloat162*)&sAh[lr][lq + j * 4 + e] = __nv_bfloat162(h0, h1);
                *(__nv_bfloat162*)&sAl[lr][lq + j * 4 + e] = __nv_bfloat162(l0, l1);
                split_bf16(xb[e], h0, l0); split_bf16(xb[e + 1], h1, l1);
                *(__nv_bfloat162*)&sBh[lr][lq + j * 4 + e] = __nv_bfloat162(h0, h1);
                *(__nv_bfloat162*)&sBl[lr][lq + j * 4 + e] = __nv_bfloat162(l0, l1);
            }
        }
        __syncthreads();
#pragma unroll
        for (int ks = 0; ks < 32; ks += 16) {
            unsigned Ah[2][4], Al[2][4], Bh[8][2], Bl[8][2];
#pragma unroll
            for (int mt = 0; mt < 2; mt++) {
                int r0 = wm * 32 + mt * 16 + g;
                Ah[mt][0] = *(const unsigned*)&sAh[r0][ks + 2 * t];
                Ah[mt][1] = *(const unsigned*)&sAh[r0 + 8][ks + 2 * t];
                Ah[mt][2] = *(const unsigned*)&sAh[r0][ks + 2 * t + 8];
                Ah[mt][3] = *(const unsigned*)&sAh[r0 + 8][ks + 2 * t + 8];
                Al[mt][0] = *(const unsigned*)&sAl[r0][ks + 2 * t];
                Al[mt][1] = *(const unsigned*)&sAl[r0 + 8][ks + 2 * t];
                Al[mt][2] = *(const unsigned*)&sAl[r0][ks + 2 * t + 8];
                Al[mt][3] = *(const unsigned*)&sAl[r0 + 8][ks + 2 * t + 8];
            }
#pragma unroll
            for (int nt = 0; nt < 8; nt++) {
                int n0 = wn * 64 + nt * 8 + g;
                Bh[nt][0] = *(const unsigned*)&sBh[n0][ks + 2 * t];
                Bh[nt][1] = *(const unsigned*)&sBh[n0][ks + 2 * t + 8];
                Bl[nt][0] = *(const unsigned*)&sBl[n0][ks + 2 * t];
                Bl[nt][1] = *(const unsigned*)&sBl[n0][ks + 2 * t + 8];
            }
#pragma unroll
            for (int mt = 0; mt < 2; mt++)
#pragma unroll
                for (int nt = 0; nt < 8; nt++) {
                    MMA16816(c[mt][nt], Ah[mt], Bh[nt]);
                    MMA16816(c[mt][nt], Al[mt], Bh[nt]);
                    MMA16816(c[mt][nt], Ah[mt], Bl[nt]);
                }
        }
    }
#pragma unroll
    for (int mt = 0; mt < 2; mt++)
#pragma unroll
        for (int nt = 0; nt < 8; nt++) {
            int row = bm + wm * 32 + mt * 16 + g;
            int col = bn + wn * 64 + nt * 8 + 2 * t;
            out[(long)row * CDIM + col] = c[mt][nt][0] + __ldg(bout + col);
            out[(long)row * CDIM + col + 1] = c[mt][nt][1] + __ldg(bout + col + 1);
            out[(long)(row + 8) * CDIM + col] = c[mt][nt][2] + __ldg(bout + col);
            out[(long)(row + 8) * CDIM + col + 1] = c[mt][nt][3] + __ldg(bout + col + 1);
        }
}

// ---------------- qr[row, v] = dot(q[row,:], rel_k_emb[v,:]) ---------------
__global__ void __launch_bounds__(256)
qr_kernel(const float* __restrict__ relk)
{
    __shared__ float sembT[CDH][132];
    __shared__ float sq[32][CDH];
    const int row0 = blockIdx.x * 32;
    for (int idx = threadIdx.x; idx < CVOCAB * CDH; idx += 256) {
        int v = idx >> 6, d = idx & 63;
        sembT[d][v] = relk[idx];
    }
    for (int d = threadIdx.x; d < CDH; d += 256) {
        sembT[d][129] = 0.f; sembT[d][130] = 0.f; sembT[d][131] = 0.f;
    }
    for (int idx = threadIdx.x; idx < 32 * CDH; idx += 256)
        sq[idx >> 6][idx & 63] = g_q[(long)row0 * CDH + idx];
    __syncthreads();

    for (int t = threadIdx.x; t < 32 * 33; t += 256) {
        int r = t / 33, vg = t % 33;
        float4 acc = make_float4(0.f, 0.f, 0.f, 0.f);
#pragma unroll 16
        for (int d = 0; d < CDH; d++) {
            float qd = sq[r][d];
            float4 e = *(const float4*)&sembT[d][vg * 4];
            acc.x += qd * e.x; acc.y += qd * e.y;
            acc.z += qd * e.z; acc.w += qd * e.w;
        }
        int v0 = vg * 4;
        long base = (long)(row0 + r) * CVOCAB + v0;
        g_qr[base + 0] = acc.x;
        if (v0 + 1 < CVOCAB) g_qr[base + 1] = acc.y;
        if (v0 + 2 < CVOCAB) g_qr[base + 2] = acc.z;
        if (v0 + 3 < CVOCAB) g_qr[base + 3] = acc.w;
    }
}

// ---------------- top-k threshold + masked softmax + rel_v weights ---------
__device__ __forceinline__ unsigned fkey(float f)
{
    unsigned u = __float_as_uint(f);
    return (u & 0x80000000u) ? ~u : (u | 0x80000000u);
}
__device__ __forceinline__ float fkeyinv(unsigned u)
{
    return __uint_as_float((u & 0x80000000u) ? (u & 0x7FFFFFFFu) : ~u);
}

__global__ void __launch_bounds__(256)
topk_softmax_w_kernel()
{
    const long row = blockIdx.x;
    const int i = (int)(row & 1023);
    float* S = g_sc + row * CN;
    __shared__ unsigned hist2[2][256];
    __shared__ float red[16];
    __shared__ float w[132];
    const int tid = threadIdx.x;
    const int lane = tid & 31, wid = tid >> 5;

    float4 v4 = ((const float4*)S)[tid];
    float v[4] = {v4.x, v4.y, v4.z, v4.w};
    unsigned u[4];
#pragma unroll
    for (int j = 0; j < 4; j++) u[j] = fkey(v[j]);
    if (tid < 132) w[tid] = 0.f;

    unsigned prefix = 0u, kk = CTOPK;   // registers, uniform across block
#pragma unroll
    for (int pass = 0; pass < 4; pass++) {
        const int shift = 24 - pass * 8;
        unsigned* hist = hist2[pass & 1];
        hist[tid] = 0u;
        __syncthreads();
#pragma unroll
        for (int j = 0; j < 4; j++) {
            bool ok = (pass == 0) || (((u[j] ^ prefix) >> (shift + 8)) == 0u);
            unsigned bin = (u[j] >> shift) & 255u;
            unsigned key = ok ? bin : 0xFFFFFFFFu;
            unsigned mm = __match_any_sync(0xFFFFFFFFu, key);
            if (ok && lane == (unsigned)(__ffs(mm) - 1))
                atomicAdd(&hist[bin], (unsigned)__popc(mm));
        }
        __syncthreads();
        // every warp redundantly scans the 256 bins (8 per lane)
        unsigned h8[8]; unsigned tot = 0;
#pragma unroll
        for (int j = 0; j < 8; j++) { h8[j] = hist[lane * 8 + j]; tot += h8[j]; }
        unsigned s = tot;
#pragma unroll
        for (int off = 1; off < 32; off <<= 1) {
            unsigned vv = __shfl_down_sync(0xFFFFFFFFu, s, off);
            if (lane + off < 32) s += vv;
        }
        unsigned prev = s - tot;         // count strictly above this lane's 8 bins
        unsigned fbin = 0xFFFFFFFFu, newk = 0;
#pragma unroll
        for (int j = 7; j >= 0; j--) {
            unsigned cur = prev + h8[j];
            if (cur >= kk && prev < kk) { fbin = lane * 8 + j; newk = kk - prev; }
            prev = cur;
        }
        unsigned msk = __ballot_sync(0xFFFFFFFFu, fbin != 0xFFFFFFFFu);
        int src = __ffs(msk) - 1;
        fbin = __shfl_sync(0xFFFFFFFFu, fbin, src);
        newk = __shfl_sync(0xFFFFFFFFu, newk, src);
        prefix |= fbin << shift;
        kk = newk;
    }
    const float thr = fkeyinv(prefix);

    // row max
    float lm = fmaxf(fmaxf(v[0], v[1]), fmaxf(v[2], v[3]));
#pragma unroll
    for (int off = 16; off > 0; off >>= 1)
        lm = fmaxf(lm, __shfl_xor_sync(0xFFFFFFFFu, lm, off));
    if (lane == 0) red[wid] = lm;
    __syncthreads();
    float mx = red[0];
#pragma unroll
    for (int q = 1; q < 8; q++) mx = fmaxf(mx, red[q]);

    float a[4];
    float ls = 0.f;
#pragma unroll
    for (int j = 0; j < 4; j++) {
        a[j] = (v[j] < thr) ? 0.f : __expf(v[j] - mx);
        ls += a[j];
    }
#pragma unroll
    for (int off = 16; off > 0; off >>= 1)
        ls += __shfl_xor_sync(0xFFFFFFFFu, ls, off);
    __syncthreads();                 // red reuse
    if (lane == 0) red[wid] = ls;
    __syncthreads();
    float sm = 0.f;
#pragma unroll
    for (int q = 0; q < 8; q++) sm += red[q];
    const float inv = 1.f / sm;
#pragma unroll
    for (int j = 0; j < 4; j++) a[j] *= inv;
    ((float4*)S)[tid] = make_float4(a[0], a[1], a[2], a[3]);

    // rel_v bucket weights: bucket(e) = clip(i-e, -64, 64) + 64
    float l0 = 0.f, l1 = 0.f;
#pragma unroll
    for (int j = 0; j < 4; j++) {
        int e = tid * 4 + j;
        int del = i - e;
        if (del <= -64) l0 += a[j];
        else if (del >= 64) l1 += a[j];
        else w[del + 64] = a[j];
    }
#pragma unroll
    for (int off = 16; off > 0; off >>= 1) {
        l0 += __shfl_xor_sync(0xFFFFFFFFu, l0, off);
        l1 += __shfl_xor_sync(0xFFFFFFFFu, l1, off);
    }
    __syncthreads();
    if (lane == 0) { red[wid] = l0; red[8 + wid] = l1; }
    __syncthreads();
    if (tid == 0) {
        float s0 = 0.f, s1 = 0.f;
#pragma unroll
        for (int q = 0; q < 8; q++) { s0 += red[q]; s1 += red[8 + q]; }
        w[0] = s0; w[128] = s1;
    }
    __syncthreads();

    if (tid < CVOCAB) g_w[row * CWSTR + tid] = w[tid];
}

// ---------------- host launcher --------------------------------------------
extern "C" void kernel_launch(void* const* d_in, const int* in_sizes, int n_in,
                              void* d_out, int out_size)
{
    (void)in_sizes; (void)n_in; (void)out_size;
    const float* x      = (const float*)d_in[0];
    const float* Wqkv   = (const float*)d_in[1];
    const float* bqkv   = (const float*)d_in[2];
    const float* Wout   = (const float*)d_in[3];
    const float* bout   = (const float*)d_in[4];
    const float* relk   = (const float*)d_in[5];
    const float* relv   = (const float*)d_in[6];
    const float* alphas = (const float*)d_in[7];
    float* out = (float*)d_out;

    float *p_q, *p_k, *p_v, *p_t0, *p_t1;
    cudaGetSymbolAddress((void**)&p_q, g_q);
    cudaGetSymbolAddress((void**)&p_k, g_k);
    cudaGetSymbolAddress((void**)&p_v, g_v);
    cudaGetSymbolAddress((void**)&p_t0, g_t0);
    cudaGetSymbolAddress((void**)&p_t1, g_t1);

    // 1a) Q,K projection (fp32 exact: feeds the top-k threshold)
    sgemm_nt<<<dim3(2048 / 128, 4096 / 128, 1), 256>>>(
        x, Wqkv, 0L, 0L, 4096, 2048, 1024, EpiQK{bqkv});

    // 1b) V projection on tensor cores (split-bf16 — V path tolerates this)
    bgemm_nt_mma<<<dim3(1024 / 128, 4096 / 128, 1), 256>>>(
        x, Wqkv + (long)2048 * 1024, 4096, 1024, 1024, EpiV{bqkv + 2048});

    // 2) q . rel_k_emb table
    qr_kernel<<<CROWS / 32, 256>>>(relk);

    // 3) scores = scale * q@k^T + qr gather (fp32 exact, batched over 64 bh)
    sgemm_nt<<<dim3(CN / 128, CN / 128, CBH), 256>>>(
        p_q, p_k, (long)CN * CDH, (long)CN * CDH, CN, CN, CDH, EpiScores{});

    // 4) exact top-256 threshold + masked softmax + rel_v bucket weights
    topk_softmax_w_kernel<<<CROWS, 256>>>();

    // 5-7) attn @ V chain on tensor cores; rel_v fused into order 0
    attnv_mma<<<dim3(CN / 128, CBH), 256>>>(p_v, p_t0, alphas, relv, 0);
    attnv_mma<<<dim3(CN / 128, CBH), 256>>>(p_t0, p_t1, alphas, relv, 1);
    attnv_mma<<<dim3(CN / 128, CBH), 256>>>(p_t1, p_t0, alphas, relv, 2);

    // 8) output projection on tensor cores, head-transpose fused into A-load
    outproj_mma<<<dim3(CDIM / 128, 4096 / 128, 1), 256>>>(Wout, bout, out);
}